// round 3
// baseline (speedup 1.0000x reference)
#include <cuda_runtime.h>

#define TT   128
#define BB   16
#define HID  1024
#define G4   4096
#define VOC  50257
#define TB   (TT*BB)                 // 2048 rows
#define LOGITS ((size_t)TB*(size_t)VOC)

// ---------------- scratch (device globals; no allocation allowed) ----------
__device__ float g_emb[TB*HID];      // embedded input          8 MB
__device__ float g_Y[2*TB*HID];      // per-layer LSTM outputs 16 MB
__device__ float g_XW[TB*G4];        // input projections      32 MB
__device__ float g_C[BB*HID];        // cell state
__device__ float g_zero[BB*HID];     // zero h0

// ---------------- packed f32x2 helpers (2x fp32 FMA rate on sm_103a) -------
__device__ __forceinline__ unsigned long long pk2(float a, float b){
    unsigned long long r;
    asm("mov.b64 %0, {%1, %2};" : "=l"(r) : "f"(a), "f"(b));
    return r;
}
__device__ __forceinline__ void upk2(unsigned long long v, float &a, float &b){
    asm("mov.b64 {%0, %1}, %2;" : "=f"(a), "=f"(b) : "l"(v));
}
__device__ __forceinline__ unsigned long long fma2(unsigned long long a,
                                                   unsigned long long b,
                                                   unsigned long long c){
    unsigned long long d;
    asm("fma.rn.f32x2 %0, %1, %2, %3;" : "=l"(d) : "l"(a), "l"(b), "l"(c));
    return d;
}

// ---------------- small utility kernels ------------------------------------
__global__ void zero_k(float* p, int n){
    for(int i = blockIdx.x*blockDim.x + threadIdx.x; i < n; i += gridDim.x*blockDim.x)
        p[i] = 0.f;
}

__global__ void embed_k(const int* __restrict__ tokens,
                        const float* __restrict__ embW,
                        float* __restrict__ X){
    int row = blockIdx.x;                    // row = t*16 + b
    int tok = tokens[row];
    const float4* src = (const float4*)(embW + (size_t)tok*HID);
    float4* dst = (float4*)(X + (size_t)row*HID);
    for(int i = threadIdx.x; i < HID/4; i += blockDim.x) dst[i] = src[i];
}

// ---------------- GEMM: C[M,N] = A[M,K] * B[N,K]^T + b1[n] (+ b2[n]) -------
// NT layout (both K-contiguous). BM=BN=128, BK=16, 256 threads, 8x8 thread
// tile with f32x2 accumulators paired over n. M,K multiples of 128/16; N ragged.
__global__ __launch_bounds__(256, 2)
void gemm_nt(const float* __restrict__ A, const float* __restrict__ Bm,
             float* __restrict__ C, const float* __restrict__ b1,
             const float* __restrict__ b2, int N, int K)
{
    __shared__ float As[16][128];
    __shared__ float Bs[16][128];
    int tid = threadIdx.x;
    int bm = blockIdx.y*128, bn = blockIdx.x*128;
    int ty = tid >> 4, tx = tid & 15;
    int m0 = ty*8, n0 = tx*8;

    unsigned long long acc[8][4];
#pragma unroll
    for(int i=0;i<8;i++)
#pragma unroll
        for(int j=0;j<4;j++) acc[i][j] = 0ull;

    int r  = tid >> 2;     // 0..63
    int c4 = tid & 3;      // float4 column within the 16-wide k tile

    for(int kt = 0; kt < K; kt += 16){
#pragma unroll
        for(int f = 0; f < 2; f++){
            int rr = r + f*64;
            float4 av = *(const float4*)(A + (size_t)(bm+rr)*K + kt + c4*4);
            As[c4*4+0][rr]=av.x; As[c4*4+1][rr]=av.y;
            As[c4*4+2][rr]=av.z; As[c4*4+3][rr]=av.w;
            int rn = bn + rr;
            float4 bv = make_float4(0.f,0.f,0.f,0.f);
            if(rn < N) bv = *(const float4*)(Bm + (size_t)rn*K + kt + c4*4);
            Bs[c4*4+0][rr]=bv.x; Bs[c4*4+1][rr]=bv.y;
            Bs[c4*4+2][rr]=bv.z; Bs[c4*4+3][rr]=bv.w;
        }
        __syncthreads();
#pragma unroll
        for(int k=0;k<16;k++){
            float a[8];
            *(float4*)(a)   = *(const float4*)&As[k][m0];
            *(float4*)(a+4) = *(const float4*)&As[k][m0+4];
            unsigned long long bd[4];
            const unsigned long long* bp = (const unsigned long long*)&Bs[k][n0];
#pragma unroll
            for(int j=0;j<4;j++) bd[j] = bp[j];
#pragma unroll
            for(int i=0;i<8;i++){
                unsigned long long ad = pk2(a[i], a[i]);
#pragma unroll
                for(int j=0;j<4;j++) acc[i][j] = fma2(ad, bd[j], acc[i][j]);
            }
        }
        __syncthreads();
    }

#pragma unroll
    for(int i=0;i<8;i++){
        size_t m = (size_t)(bm + m0 + i);
#pragma unroll
        for(int j=0;j<4;j++){
            float x, y; upk2(acc[i][j], x, y);
            int n = bn + n0 + j*2;
            if(n < N){
                float bb = b1[n] + (b2 ? b2[n] : 0.f);
                C[m*(size_t)N + n] = x + bb;
            }
            if(n+1 < N){
                float bb = b1[n+1] + (b2 ? b2[n+1] : 0.f);
                C[m*(size_t)N + n+1] = y + bb;
            }
        }
    }
}

// ---------------- fused LSTM step -------------------------------------------
// gates[b, j] = XW_t[b, j] + dot(h_prev[b,:], Whh[j,:])  then cell update.
// grid = 128 blocks (8 hidden units each => 32 gate rows), 256 threads.
// Each warp: 4 gate rows x all 16 batches, Whh streamed from L2 once per step,
// h staged in smem, f32x2 accumulators paired over batch.
__global__ void lstm_step(const float* __restrict__ hprev,
                          const float* __restrict__ Whh,
                          const float* __restrict__ XWt,
                          float* __restrict__ Cst,
                          float* __restrict__ Yout,
                          float* __restrict__ hT,
                          float* __restrict__ cT)
{
    extern __shared__ float sm[];
    float* h_s   = sm;                 // 16*1024 floats
    float* gates = sm + BB*HID;        // 4*8*16 floats
    int tid = threadIdx.x;

    { // stage h_prev
        const float4* src = (const float4*)hprev;
        float4* dst = (float4*)h_s;
        for(int i = tid; i < BB*HID/4; i += 256) dst[i] = src[i];
    }
    __syncthreads();

    int w = tid >> 5, lane = tid & 31;
    int g = w >> 1, rbase = (w & 1)*4;     // gate type, row-subrange
    int ub = blockIdx.x*8;                 // hidden-unit tile base

    const float* wr[4];
#pragma unroll
    for(int jj=0;jj<4;jj++)
        wr[jj] = Whh + (size_t)(g*HID + ub + rbase + jj)*HID;

    unsigned long long acc[4][8];
#pragma unroll
    for(int jj=0;jj<4;jj++)
#pragma unroll
        for(int p=0;p<8;p++) acc[jj][p] = 0ull;

    for(int c = 0; c < 32; c++){
        int k = c*32 + lane;
        unsigned long long hp[8];
#pragma unroll
        for(int p=0;p<8;p++)
            hp[p] = pk2(h_s[(2*p)*HID + k], h_s[(2*p+1)*HID + k]);
#pragma unroll
        for(int jj=0;jj<4;jj++){
            float wv = wr[jj][k];
            unsigned long long wd = pk2(wv, wv);
#pragma unroll
            for(int p=0;p<8;p++) acc[jj][p] = fma2(wd, hp[p], acc[jj][p]);
        }
    }

    // cross-lane reduction of 4x16 partial dots
    float red[4][16];
#pragma unroll
    for(int jj=0;jj<4;jj++)
#pragma unroll
        for(int p=0;p<8;p++) upk2(acc[jj][p], red[jj][2*p], red[jj][2*p+1]);
#pragma unroll
    for(int jj=0;jj<4;jj++)
#pragma unroll
        for(int b=0;b<16;b++)
#pragma unroll
            for(int o=16;o>0;o>>=1)
                red[jj][b] += __shfl_xor_sync(0xffffffffu, red[jj][b], o);

    if(lane < 16){
#pragma unroll
        for(int jj=0;jj<4;jj++){
            int rloc = rbase + jj;
            float gate = red[jj][lane] +
                         XWt[(size_t)lane*G4 + g*HID + ub + rloc];
            gates[(g*8 + rloc)*16 + lane] = gate;
        }
    }
    __syncthreads();

    if(tid < 128){
        int ul = tid >> 4, b = tid & 15;
        float iv = gates[(0*8+ul)*16 + b];
        float fv = gates[(1*8+ul)*16 + b];
        float gv = gates[(2*8+ul)*16 + b];
        float ov = gates[(3*8+ul)*16 + b];
        iv = 1.f/(1.f + __expf(-iv));
        fv = 1.f/(1.f + __expf(-fv));
        ov = 1.f/(1.f + __expf(-ov));
        gv = tanhf(gv);
        int u = ub + ul;
        float co = Cst[b*HID + u];
        float cn = fv*co + iv*gv;
        float hn = ov*tanhf(cn);
        Cst[b*HID + u]  = cn;
        Yout[b*HID + u] = hn;
        if(hT){ hT[b*HID + u] = hn; cT[b*HID + u] = cn; }
    }
}

// ---------------- row-wise log_softmax over 50257, in place -----------------
__global__ void logsoftmax_k(float* __restrict__ p0){
    __shared__ float red[33];
    int row = blockIdx.x;
    float* p = p0 + (size_t)row*(size_t)VOC;
    int tid = threadIdx.x, lane = tid & 31, w = tid >> 5;
    int nthr = blockDim.x, nw = nthr >> 5;

    float m = -3.4e38f;
    for(int i = tid; i < VOC; i += nthr) m = fmaxf(m, p[i]);
#pragma unroll
    for(int o=16;o>0;o>>=1) m = fmaxf(m, __shfl_xor_sync(0xffffffffu, m, o));
    if(lane == 0) red[w] = m;
    __syncthreads();
    if(tid == 0){
        float mm = red[0];
        for(int i=1;i<nw;i++) mm = fmaxf(mm, red[i]);
        red[32] = mm;
    }
    __syncthreads();
    float M = red[32];

    float s = 0.f;
    for(int i = tid; i < VOC; i += nthr) s += __expf(p[i] - M);
#pragma unroll
    for(int o=16;o>0;o>>=1) s += __shfl_xor_sync(0xffffffffu, s, o);
    __syncthreads();
    if(lane == 0) red[w] = s;
    __syncthreads();
    if(tid == 0){
        float ss = 0.f;
        for(int i=0;i<nw;i++) ss += red[i];
        red[32] = M + logf(ss);
    }
    __syncthreads();
    float lse = red[32];
    for(int i = tid; i < VOC; i += nthr) p[i] -= lse;
}

// ---------------- launcher ---------------------------------------------------
extern "C" void kernel_launch(void* const* d_in, const int* in_sizes, int n_in,
                              void* d_out, int out_size)
{
    const int*   tokens = (const int*)  d_in[0];
    const float* embW   = (const float*)d_in[1];
    const float* Wih    = (const float*)d_in[2];
    const float* Whh    = (const float*)d_in[3];
    const float* bih    = (const float*)d_in[4];
    const float* bhh    = (const float*)d_in[5];
    const float* decW   = (const float*)d_in[6];
    const float* decb   = (const float*)d_in[7];
    float* out = (float*)d_out;

    float *pEmb,*pY,*pXW,*pC,*pZ;
    cudaGetSymbolAddress((void**)&pEmb, g_emb);
    cudaGetSymbolAddress((void**)&pY,   g_Y);
    cudaGetSymbolAddress((void**)&pXW,  g_XW);
    cudaGetSymbolAddress((void**)&pC,   g_C);
    cudaGetSymbolAddress((void**)&pZ,   g_zero);

    const int STEP_SMEM = (BB*HID + 4*8*16)*4;   // 67584 B
    cudaFuncSetAttribute(lstm_step, cudaFuncAttributeMaxDynamicSharedMemorySize,
                         STEP_SMEM);

    embed_k<<<TB, 256>>>(tokens, embW, pEmb);
    zero_k<<<64, 256>>>(pZ, BB*HID);

    for(int l = 0; l < 2; l++){
        const float* Xin = (l == 0) ? pEmb : pY;            // layer0 output at pY
        float* Yl = pY + (size_t)l*TB*HID;
        zero_k<<<64, 256>>>(pC, BB*HID);
        gemm_nt<<<dim3(G4/128, TB/128), 256>>>(Xin, Wih + (size_t)l*G4*HID,
                                               pXW, bih + l*G4, bhh + l*G4,
                                               G4, HID);
        for(int t = 0; t < TT; t++){
            const float* hp = (t == 0) ? pZ : (Yl + (size_t)(t-1)*BB*HID);
            float *hT = nullptr, *cT = nullptr;
            if(t == TT-1){
                hT = out + LOGITS + (size_t)l*BB*HID;
                cT = out + LOGITS + (size_t)(2 + l)*BB*HID;
            }
            lstm_step<<<128, 256, STEP_SMEM>>>(hp, Whh + (size_t)l*G4*HID,
                                               pXW + (size_t)t*BB*G4, pC,
                                               Yl + (size_t)t*BB*HID, hT, cT);
        }
    }

    gemm_nt<<<dim3((VOC+127)/128, TB/128), 256>>>(pY + (size_t)TB*HID, decW,
                                                  out, decb, nullptr, VOC, HID);
    logsoftmax_k<<<TB, 512>>>(out);
}

// round 4
// speedup vs baseline: 1.0014x; 1.0014x over previous
#include <cuda_runtime.h>

#define TT   128
#define BB   16
#define HID  1024
#define G4   4096
#define VOC  50257
#define TB   (TT*BB)                 // 2048 rows
#define LOGITS ((size_t)TB*(size_t)VOC)

// ---------------- scratch (device globals; no allocation allowed) ----------
__device__ float g_emb[TB*HID];      // embedded input          8 MB
__device__ float g_Y[2*TB*HID];      // per-layer LSTM outputs 16 MB
__device__ float g_XW[TB*G4];        // input projections      32 MB
__device__ float g_C[BB*HID];        // cell state
__device__ float g_zero[BB*HID];     // zero h0

// ---------------- packed f32x2 helpers (2x fp32 FMA rate on sm_103a) -------
__device__ __forceinline__ unsigned long long pk2(float a, float b){
    unsigned long long r;
    asm("mov.b64 %0, {%1, %2};" : "=l"(r) : "f"(a), "f"(b));
    return r;
}
__device__ __forceinline__ void upk2(unsigned long long v, float &a, float &b){
    asm("mov.b64 {%0, %1}, %2;" : "=f"(a), "=f"(b) : "l"(v));
}
__device__ __forceinline__ unsigned long long fma2(unsigned long long a,
                                                   unsigned long long b,
                                                   unsigned long long c){
    unsigned long long d;
    asm("fma.rn.f32x2 %0, %1, %2, %3;" : "=l"(d) : "l"(a), "l"(b), "l"(c));
    return d;
}

// ---------------- small utility kernels ------------------------------------
__global__ void zero_k(float* p, int n){
    for(int i = blockIdx.x*blockDim.x + threadIdx.x; i < n; i += gridDim.x*blockDim.x)
        p[i] = 0.f;
}

__global__ void embed_k(const int* __restrict__ tokens,
                        const float* __restrict__ embW,
                        float* __restrict__ X){
    int row = blockIdx.x;                    // row = t*16 + b
    int tok = tokens[row];
    const float4* src = (const float4*)(embW + (size_t)tok*HID);
    float4* dst = (float4*)(X + (size_t)row*HID);
    for(int i = threadIdx.x; i < HID/4; i += blockDim.x) dst[i] = src[i];
}

// ---------------- GEMM: C[M,N] = A[M,K] * B[N,K]^T + b1[n] (+ b2[n]) -------
// NT layout (both K-contiguous). BM=BN=128, BK=16, 256 threads, 8x8 thread
// tile with f32x2 accumulators paired over n. M,K multiples of 128/16; N ragged.
__global__ __launch_bounds__(256, 2)
void gemm_nt(const float* __restrict__ A, const float* __restrict__ Bm,
             float* __restrict__ C, const float* __restrict__ b1,
             const float* __restrict__ b2, int N, int K)
{
    __shared__ float As[16][128];
    __shared__ float Bs[16][128];
    int tid = threadIdx.x;
    int bm = blockIdx.y*128, bn = blockIdx.x*128;
    int ty = tid >> 4, tx = tid & 15;
    int m0 = ty*8, n0 = tx*8;

    unsigned long long acc[8][4];
#pragma unroll
    for(int i=0;i<8;i++)
#pragma unroll
        for(int j=0;j<4;j++) acc[i][j] = 0ull;

    int r  = tid >> 2;     // 0..63
    int c4 = tid & 3;      // float4 column within the 16-wide k tile

    for(int kt = 0; kt < K; kt += 16){
#pragma unroll
        for(int f = 0; f < 2; f++){
            int rr = r + f*64;
            float4 av = *(const float4*)(A + (size_t)(bm+rr)*K + kt + c4*4);
            As[c4*4+0][rr]=av.x; As[c4*4+1][rr]=av.y;
            As[c4*4+2][rr]=av.z; As[c4*4+3][rr]=av.w;
            int rn = bn + rr;
            float4 bv = make_float4(0.f,0.f,0.f,0.f);
            if(rn < N) bv = *(const float4*)(Bm + (size_t)rn*K + kt + c4*4);
            Bs[c4*4+0][rr]=bv.x; Bs[c4*4+1][rr]=bv.y;
            Bs[c4*4+2][rr]=bv.z; Bs[c4*4+3][rr]=bv.w;
        }
        __syncthreads();
#pragma unroll
        for(int k=0;k<16;k++){
            float a[8];
            *(float4*)(a)   = *(const float4*)&As[k][m0];
            *(float4*)(a+4) = *(const float4*)&As[k][m0+4];
            unsigned long long bd[4];
            const unsigned long long* bp = (const unsigned long long*)&Bs[k][n0];
#pragma unroll
            for(int j=0;j<4;j++) bd[j] = bp[j];
#pragma unroll
            for(int i=0;i<8;i++){
                unsigned long long ad = pk2(a[i], a[i]);
#pragma unroll
                for(int j=0;j<4;j++) acc[i][j] = fma2(ad, bd[j], acc[i][j]);
            }
        }
        __syncthreads();
    }

#pragma unroll
    for(int i=0;i<8;i++){
        size_t m = (size_t)(bm + m0 + i);
#pragma unroll
        for(int j=0;j<4;j++){
            float x, y; upk2(acc[i][j], x, y);
            int n = bn + n0 + j*2;
            if(n < N){
                float bb = b1[n] + (b2 ? b2[n] : 0.f);
                C[m*(size_t)N + n] = x + bb;
            }
            if(n+1 < N){
                float bb = b1[n+1] + (b2 ? b2[n+1] : 0.f);
                C[m*(size_t)N + n+1] = y + bb;
            }
        }
    }
}

// ---------------- fused LSTM step -------------------------------------------
// gates[b, j] = XW_t[b, j] + dot(h_prev[b,:], Whh[j,:])  then cell update.
// grid = 128 blocks (8 hidden units each => 32 gate rows), 256 threads.
// Each warp: 4 gate rows x all 16 batches, Whh streamed from L2 once per step,
// h staged in smem, f32x2 accumulators paired over batch.
__global__ void lstm_step(const float* __restrict__ hprev,
                          const float* __restrict__ Whh,
                          const float* __restrict__ XWt,
                          float* __restrict__ Cst,
                          float* __restrict__ Yout,
                          float* __restrict__ hT,
                          float* __restrict__ cT)
{
    extern __shared__ float sm[];
    float* h_s   = sm;                 // 16*1024 floats
    float* gates = sm + BB*HID;        // 4*8*16 floats
    int tid = threadIdx.x;

    { // stage h_prev
        const float4* src = (const float4*)hprev;
        float4* dst = (float4*)h_s;
        for(int i = tid; i < BB*HID/4; i += 256) dst[i] = src[i];
    }
    __syncthreads();

    int w = tid >> 5, lane = tid & 31;
    int g = w >> 1, rbase = (w & 1)*4;     // gate type, row-subrange
    int ub = blockIdx.x*8;                 // hidden-unit tile base

    const float* wr[4];
#pragma unroll
    for(int jj=0;jj<4;jj++)
        wr[jj] = Whh + (size_t)(g*HID + ub + rbase + jj)*HID;

    unsigned long long acc[4][8];
#pragma unroll
    for(int jj=0;jj<4;jj++)
#pragma unroll
        for(int p=0;p<8;p++) acc[jj][p] = 0ull;

    for(int c = 0; c < 32; c++){
        int k = c*32 + lane;
        unsigned long long hp[8];
#pragma unroll
        for(int p=0;p<8;p++)
            hp[p] = pk2(h_s[(2*p)*HID + k], h_s[(2*p+1)*HID + k]);
#pragma unroll
        for(int jj=0;jj<4;jj++){
            float wv = wr[jj][k];
            unsigned long long wd = pk2(wv, wv);
#pragma unroll
            for(int p=0;p<8;p++) acc[jj][p] = fma2(wd, hp[p], acc[jj][p]);
        }
    }

    // cross-lane reduction of 4x16 partial dots
    float red[4][16];
#pragma unroll
    for(int jj=0;jj<4;jj++)
#pragma unroll
        for(int p=0;p<8;p++) upk2(acc[jj][p], red[jj][2*p], red[jj][2*p+1]);
#pragma unroll
    for(int jj=0;jj<4;jj++)
#pragma unroll
        for(int b=0;b<16;b++)
#pragma unroll
            for(int o=16;o>0;o>>=1)
                red[jj][b] += __shfl_xor_sync(0xffffffffu, red[jj][b], o);

    if(lane < 16){
#pragma unroll
        for(int jj=0;jj<4;jj++){
            int rloc = rbase + jj;
            float gate = red[jj][lane] +
                         XWt[(size_t)lane*G4 + g*HID + ub + rloc];
            gates[(g*8 + rloc)*16 + lane] = gate;
        }
    }
    __syncthreads();

    if(tid < 128){
        int ul = tid >> 4, b = tid & 15;
        float iv = gates[(0*8+ul)*16 + b];
        float fv = gates[(1*8+ul)*16 + b];
        float gv = gates[(2*8+ul)*16 + b];
        float ov = gates[(3*8+ul)*16 + b];
        iv = 1.f/(1.f + __expf(-iv));
        fv = 1.f/(1.f + __expf(-fv));
        ov = 1.f/(1.f + __expf(-ov));
        gv = tanhf(gv);
        int u = ub + ul;
        float co = Cst[b*HID + u];
        float cn = fv*co + iv*gv;
        float hn = ov*tanhf(cn);
        Cst[b*HID + u]  = cn;
        Yout[b*HID + u] = hn;
        if(hT){ hT[b*HID + u] = hn; cT[b*HID + u] = cn; }
    }
}

// ---------------- row-wise log_softmax over 50257, in place -----------------
__global__ void logsoftmax_k(float* __restrict__ p0){
    __shared__ float red[33];
    int row = blockIdx.x;
    float* p = p0 + (size_t)row*(size_t)VOC;
    int tid = threadIdx.x, lane = tid & 31, w = tid >> 5;
    int nthr = blockDim.x, nw = nthr >> 5;

    float m = -3.4e38f;
    for(int i = tid; i < VOC; i += nthr) m = fmaxf(m, p[i]);
#pragma unroll
    for(int o=16;o>0;o>>=1) m = fmaxf(m, __shfl_xor_sync(0xffffffffu, m, o));
    if(lane == 0) red[w] = m;
    __syncthreads();
    if(tid == 0){
        float mm = red[0];
        for(int i=1;i<nw;i++) mm = fmaxf(mm, red[i]);
        red[32] = mm;
    }
    __syncthreads();
    float M = red[32];

    float s = 0.f;
    for(int i = tid; i < VOC; i += nthr) s += __expf(p[i] - M);
#pragma unroll
    for(int o=16;o>0;o>>=1) s += __shfl_xor_sync(0xffffffffu, s, o);
    __syncthreads();
    if(lane == 0) red[w] = s;
    __syncthreads();
    if(tid == 0){
        float ss = 0.f;
        for(int i=0;i<nw;i++) ss += red[i];
        red[32] = M + logf(ss);
    }
    __syncthreads();
    float lse = red[32];
    for(int i = tid; i < VOC; i += nthr) p[i] -= lse;
}

// ---------------- launcher ---------------------------------------------------
extern "C" void kernel_launch(void* const* d_in, const int* in_sizes, int n_in,
                              void* d_out, int out_size)
{
    const int*   tokens = (const int*)  d_in[0];
    const float* embW   = (const float*)d_in[1];
    const float* Wih    = (const float*)d_in[2];
    const float* Whh    = (const float*)d_in[3];
    const float* bih    = (const float*)d_in[4];
    const float* bhh    = (const float*)d_in[5];
    const float* decW   = (const float*)d_in[6];
    const float* decb   = (const float*)d_in[7];
    float* out = (float*)d_out;

    float *pEmb,*pY,*pXW,*pC,*pZ;
    cudaGetSymbolAddress((void**)&pEmb, g_emb);
    cudaGetSymbolAddress((void**)&pY,   g_Y);
    cudaGetSymbolAddress((void**)&pXW,  g_XW);
    cudaGetSymbolAddress((void**)&pC,   g_C);
    cudaGetSymbolAddress((void**)&pZ,   g_zero);

    const int STEP_SMEM = (BB*HID + 4*8*16)*4;   // 67584 B
    cudaFuncSetAttribute(lstm_step, cudaFuncAttributeMaxDynamicSharedMemorySize,
                         STEP_SMEM);

    embed_k<<<TB, 256>>>(tokens, embW, pEmb);
    zero_k<<<64, 256>>>(pZ, BB*HID);

    for(int l = 0; l < 2; l++){
        const float* Xin = (l == 0) ? pEmb : pY;            // layer0 output at pY
        float* Yl = pY + (size_t)l*TB*HID;
        zero_k<<<64, 256>>>(pC, BB*HID);
        gemm_nt<<<dim3(G4/128, TB/128), 256>>>(Xin, Wih + (size_t)l*G4*HID,
                                               pXW, bih + l*G4, bhh + l*G4,
                                               G4, HID);
        for(int t = 0; t < TT; t++){
            const float* hp = (t == 0) ? pZ : (Yl + (size_t)(t-1)*BB*HID);
            float *hT = nullptr, *cT = nullptr;
            if(t == TT-1){
                hT = out + LOGITS + (size_t)l*BB*HID;
                cT = out + LOGITS + (size_t)(2 + l)*BB*HID;
            }
            lstm_step<<<128, 256, STEP_SMEM>>>(hp, Whh + (size_t)l*G4*HID,
                                               pXW + (size_t)t*BB*G4, pC,
                                               Yl + (size_t)t*BB*HID, hT, cT);
        }
    }

    gemm_nt<<<dim3((VOC+127)/128, TB/128), 256>>>(pY + (size_t)TB*HID, decW,
                                                  out, decb, nullptr, VOC, HID);
    logsoftmax_k<<<TB, 512>>>(out);
}

// round 7
// speedup vs baseline: 1.5524x; 1.5503x over previous
#include <cuda_runtime.h>
#include <cstdint>

#define TT   128
#define BB   16
#define HID  1024
#define G4   4096
#define VOC  50257
#define TB   (TT*BB)                 // 2048 rows
#define LOGITS ((size_t)TB*(size_t)VOC)

// ---------------- scratch (device globals; no allocation allowed) ----------
__device__ float g_emb[TB*HID];      // embedded input          8 MB
__device__ float g_Y[2*TB*HID];      // per-layer LSTM outputs 16 MB
__device__ float g_XW[TB*G4];        // input projections      32 MB
__device__ float g_C[BB*HID];        // cell state
__device__ float g_zero[BB*HID];     // zero h0

// ---------------- packed f32x2 helpers (2x fp32 FMA rate on sm_103a) -------
__device__ __forceinline__ unsigned long long pk2(float a, float b){
    unsigned long long r;
    asm("mov.b64 %0, {%1, %2};" : "=l"(r) : "f"(a), "f"(b));
    return r;
}
__device__ __forceinline__ void upk2(unsigned long long v, float &a, float &b){
    asm("mov.b64 {%0, %1}, %2;" : "=f"(a), "=f"(b) : "l"(v));
}
__device__ __forceinline__ unsigned long long fma2(unsigned long long a,
                                                   unsigned long long b,
                                                   unsigned long long c){
    unsigned long long d;
    asm("fma.rn.f32x2 %0, %1, %2, %3;" : "=l"(d) : "l"(a), "l"(b), "l"(c));
    return d;
}

// ---------------- tf32 helpers ----------------------------------------------
__device__ __forceinline__ uint32_t f2t(float x){
    uint32_t u;
    asm("cvt.rna.tf32.f32 %0, %1;" : "=r"(u) : "f"(x));
    return u;
}
__device__ __forceinline__ void mma_tf32(float* c, const uint32_t* a,
                                         const uint32_t* b){
    asm volatile(
        "mma.sync.aligned.m16n8k8.row.col.f32.tf32.tf32.f32 "
        "{%0,%1,%2,%3}, {%4,%5,%6,%7}, {%8,%9}, {%0,%1,%2,%3};"
        : "+f"(c[0]), "+f"(c[1]), "+f"(c[2]), "+f"(c[3])
        : "r"(a[0]), "r"(a[1]), "r"(a[2]), "r"(a[3]), "r"(b[0]), "r"(b[1]));
}
__device__ __forceinline__ uint32_t smem_u32(const void* p){
    uint32_t a;
    asm("{ .reg .u64 t; cvta.to.shared.u64 t, %1; cvt.u32.u64 %0, t; }"
        : "=r"(a) : "l"(p));
    return a;
}
__device__ __forceinline__ void cpa16(uint32_t dst, const void* src, int sz){
    asm volatile("cp.async.cg.shared.global [%0], [%1], 16, %2;"
                 :: "r"(dst), "l"(src), "r"(sz) : "memory");
}
__device__ __forceinline__ void cpa_wait_all(){
    asm volatile("cp.async.wait_all;" ::: "memory");
}

// ---------------- small utility kernels ------------------------------------
__global__ void zero_k(float* p, int n){
    for(int i = blockIdx.x*blockDim.x + threadIdx.x; i < n; i += gridDim.x*blockDim.x)
        p[i] = 0.f;
}

__global__ void embed_k(const int* __restrict__ tokens,
                        const float* __restrict__ embW,
                        float* __restrict__ X){
    int row = blockIdx.x;                    // row = t*16 + b
    int tok = tokens[row];
    const float4* src = (const float4*)(embW + (size_t)tok*HID);
    float4* dst = (float4*)(X + (size_t)row*HID);
    for(int i = threadIdx.x; i < HID/4; i += blockDim.x) dst[i] = src[i];
}

// ---------------- tf32 tensor-core GEMM (HMMA via mma.sync) -----------------
// C[M,N] = A[M,K] * B[N,K]^T + b1[n] (+ b2[n]).  NT, both K-contiguous.
// BM=128, BN=128, BK=32. 256 threads = 8 warps in 2(M) x 4(N); warp tile
// 64x32 = 4x4 m16n8k8 tf32 mma.sync. fp32 accumulate. SMEM row stride 36
// floats => conflict-free fragment loads. M,K multiples of 128/32; N ragged
// (OOB B rows zero-filled via cp.async src-size 0; OOB stores guarded).
#define TCP 36                       // padded smem row stride (floats)
__global__ __launch_bounds__(256, 2)
void gemm_tc(const float* __restrict__ A, const float* __restrict__ Bm,
             float* __restrict__ C, const float* __restrict__ b1,
             const float* __restrict__ b2, int N, int K)
{
    __shared__ float As[128*TCP];
    __shared__ float Bs[128*TCP];
    const int tid = threadIdx.x;
    const int wid = tid >> 5, lane = tid & 31;
    const int r = lane >> 2, cc = lane & 3;
    const int wm = (wid & 1) * 64;          // warp M offset
    const int wn = (wid >> 1) * 32;         // warp N offset
    const int bm = blockIdx.y * 128, bn = blockIdx.x * 128;

    const uint32_t sA = smem_u32(As), sB = smem_u32(Bs);

    float acc[4][4][4];
#pragma unroll
    for(int mi=0;mi<4;mi++)
#pragma unroll
        for(int ni=0;ni<4;ni++)
#pragma unroll
            for(int q=0;q<4;q++) acc[mi][ni][q] = 0.f;

    // per-thread load coords: 128 rows x 8 float4 = 1024 float4 per tile;
    // 2 threads per row, each loads 4 consecutive float4 => full coverage.
    const int lm = tid >> 1;                // row 0..127
    const int lq0 = (tid & 1) * 4;          // float4 slot base: 0 or 4

    for(int kt = 0; kt < K; kt += 32){
#pragma unroll
        for(int h = 0; h < 4; h++){
            int q = lq0 + h;                // float4 index 0..7 within 32-float row
            // A tile
            cpa16(sA + (uint32_t)(lm*TCP + q*4)*4,
                  A + (size_t)(bm + lm)*K + kt + q*4, 16);
            // B tile (guard ragged N)
            int rowb = bn + lm;
            int ok = (rowb < N) ? 16 : 0;
            cpa16(sB + (uint32_t)(lm*TCP + q*4)*4,
                  Bm + (size_t)(ok ? rowb : 0)*K + kt + q*4, ok);
        }
        cpa_wait_all();
        __syncthreads();

#pragma unroll
        for(int ks = 0; ks < 4; ks++){
            const int k0 = ks*8;
            uint32_t af[4][4], bf[4][2];
#pragma unroll
            for(int mi=0;mi<4;mi++){
                const float* ap = As + (wm + mi*16 + r)*TCP + k0 + cc;
                af[mi][0] = f2t(ap[0]);
                af[mi][1] = f2t(ap[8*TCP]);
                af[mi][2] = f2t(ap[4]);
                af[mi][3] = f2t(ap[8*TCP + 4]);
            }
#pragma unroll
            for(int ni=0;ni<4;ni++){
                const float* bp = Bs + (wn + ni*8 + r)*TCP + k0 + cc;
                bf[ni][0] = f2t(bp[0]);
                bf[ni][1] = f2t(bp[4]);
            }
#pragma unroll
            for(int mi=0;mi<4;mi++)
#pragma unroll
                for(int ni=0;ni<4;ni++)
                    mma_tf32(acc[mi][ni], af[mi], bf[ni]);
        }
        __syncthreads();
    }

    // epilogue: each thread owns (row, row+8) x (col, col+1) per (mi, ni)
#pragma unroll
    for(int ni=0;ni<4;ni++){
        int col = bn + wn + ni*8 + 2*cc;
        if(col >= N) continue;
        bool c1ok = (col + 1 < N);
        float bb0 = b1[col] + (b2 ? b2[col] : 0.f);
        float bb1 = c1ok ? (b1[col+1] + (b2 ? b2[col+1] : 0.f)) : 0.f;
#pragma unroll
        for(int mi=0;mi<4;mi++){
            size_t row0 = (size_t)(bm + wm + mi*16 + r);
            float* p0 = C + row0*(size_t)N + col;
            float* p1 = C + (row0+8)*(size_t)N + col;
            p0[0] = acc[mi][ni][0] + bb0;
            if(c1ok) p0[1] = acc[mi][ni][1] + bb1;
            p1[0] = acc[mi][ni][2] + bb0;
            if(c1ok) p1[1] = acc[mi][ni][3] + bb1;
        }
    }
}

// ---------------- fused LSTM step -------------------------------------------
__global__ void lstm_step(const float* __restrict__ hprev,
                          const float* __restrict__ Whh,
                          const float* __restrict__ XWt,
                          float* __restrict__ Cst,
                          float* __restrict__ Yout,
                          float* __restrict__ hT,
                          float* __restrict__ cT)
{
    extern __shared__ float sm[];
    float* h_s   = sm;                 // 16*1024 floats
    float* gates = sm + BB*HID;        // 4*8*16 floats
    int tid = threadIdx.x;

    { // stage h_prev
        const float4* src = (const float4*)hprev;
        float4* dst = (float4*)h_s;
        for(int i = tid; i < BB*HID/4; i += 256) dst[i] = src[i];
    }
    __syncthreads();

    int w = tid >> 5, lane = tid & 31;
    int g = w >> 1, rbase = (w & 1)*4;
    int ub = blockIdx.x*8;

    const float* wr[4];
#pragma unroll
    for(int jj=0;jj<4;jj++)
        wr[jj] = Whh + (size_t)(g*HID + ub + rbase + jj)*HID;

    unsigned long long acc[4][8];
#pragma unroll
    for(int jj=0;jj<4;jj++)
#pragma unroll
        for(int p=0;p<8;p++) acc[jj][p] = 0ull;

    for(int c = 0; c < 32; c++){
        int k = c*32 + lane;
        unsigned long long hp[8];
#pragma unroll
        for(int p=0;p<8;p++)
            hp[p] = pk2(h_s[(2*p)*HID + k], h_s[(2*p+1)*HID + k]);
#pragma unroll
        for(int jj=0;jj<4;jj++){
            float wv = wr[jj][k];
            unsigned long long wd = pk2(wv, wv);
#pragma unroll
            for(int p=0;p<8;p++) acc[jj][p] = fma2(wd, hp[p], acc[jj][p]);
        }
    }

    float red[4][16];
#pragma unroll
    for(int jj=0;jj<4;jj++)
#pragma unroll
        for(int p=0;p<8;p++) upk2(acc[jj][p], red[jj][2*p], red[jj][2*p+1]);
#pragma unroll
    for(int jj=0;jj<4;jj++)
#pragma unroll
        for(int b=0;b<16;b++)
#pragma unroll
            for(int o=16;o>0;o>>=1)
                red[jj][b] += __shfl_xor_sync(0xffffffffu, red[jj][b], o);

    if(lane < 16){
#pragma unroll
        for(int jj=0;jj<4;jj++){
            int rloc = rbase + jj;
            float gate = red[jj][lane] +
                         XWt[(size_t)lane*G4 + g*HID + ub + rloc];
            gates[(g*8 + rloc)*16 + lane] = gate;
        }
    }
    __syncthreads();

    if(tid < 128){
        int ul = tid >> 4, b = tid & 15;
        float iv = gates[(0*8+ul)*16 + b];
        float fv = gates[(1*8+ul)*16 + b];
        float gv = gates[(2*8+ul)*16 + b];
        float ov = gates[(3*8+ul)*16 + b];
        iv = 1.f/(1.f + __expf(-iv));
        fv = 1.f/(1.f + __expf(-fv));
        ov = 1.f/(1.f + __expf(-ov));
        gv = tanhf(gv);
        int u = ub + ul;
        float co = Cst[b*HID + u];
        float cn = fv*co + iv*gv;
        float hn = ov*tanhf(cn);
        Cst[b*HID + u]  = cn;
        Yout[b*HID + u] = hn;
        if(hT){ hT[b*HID + u] = hn; cT[b*HID + u] = cn; }
    }
}

// ---------------- row-wise log_softmax over 50257, in place -----------------
__global__ void logsoftmax_k(float* __restrict__ p0){
    __shared__ float red[33];
    int row = blockIdx.x;
    float* p = p0 + (size_t)row*(size_t)VOC;
    int tid = threadIdx.x, lane = tid & 31, w = tid >> 5;
    int nthr = blockDim.x, nw = nthr >> 5;

    float m = -3.4e38f;
    for(int i = tid; i < VOC; i += nthr) m = fmaxf(m, p[i]);
#pragma unroll
    for(int o=16;o>0;o>>=1) m = fmaxf(m, __shfl_xor_sync(0xffffffffu, m, o));
    if(lane == 0) red[w] = m;
    __syncthreads();
    if(tid == 0){
        float mm = red[0];
        for(int i=1;i<nw;i++) mm = fmaxf(mm, red[i]);
        red[32] = mm;
    }
    __syncthreads();
    float M = red[32];

    float s = 0.f;
    for(int i = tid; i < VOC; i += nthr) s += __expf(p[i] - M);
#pragma unroll
    for(int o=16;o>0;o>>=1) s += __shfl_xor_sync(0xffffffffu, s, o);
    __syncthreads();
    if(lane == 0) red[w] = s;
    __syncthreads();
    if(tid == 0){
        float ss = 0.f;
        for(int i=0;i<nw;i++) ss += red[i];
        red[32] = M + logf(ss);
    }
    __syncthreads();
    float lse = red[32];
    for(int i = tid; i < VOC; i += nthr) p[i] -= lse;
}

// ---------------- launcher ---------------------------------------------------
extern "C" void kernel_launch(void* const* d_in, const int* in_sizes, int n_in,
                              void* d_out, int out_size)
{
    const int*   tokens = (const int*)  d_in[0];
    const float* embW   = (const float*)d_in[1];
    const float* Wih    = (const float*)d_in[2];
    const float* Whh    = (const float*)d_in[3];
    const float* bih    = (const float*)d_in[4];
    const float* bhh    = (const float*)d_in[5];
    const float* decW   = (const float*)d_in[6];
    const float* decb   = (const float*)d_in[7];
    float* out = (float*)d_out;

    float *pEmb,*pY,*pXW,*pC,*pZ;
    cudaGetSymbolAddress((void**)&pEmb, g_emb);
    cudaGetSymbolAddress((void**)&pY,   g_Y);
    cudaGetSymbolAddress((void**)&pXW,  g_XW);
    cudaGetSymbolAddress((void**)&pC,   g_C);
    cudaGetSymbolAddress((void**)&pZ,   g_zero);

    const int STEP_SMEM = (BB*HID + 4*8*16)*4;   // 67584 B
    cudaFuncSetAttribute(lstm_step, cudaFuncAttributeMaxDynamicSharedMemorySize,
                         STEP_SMEM);

    embed_k<<<TB, 256>>>(tokens, embW, pEmb);
    zero_k<<<64, 256>>>(pZ, BB*HID);

    for(int l = 0; l < 2; l++){
        const float* Xin = (l == 0) ? pEmb : pY;            // layer0 output at pY
        float* Yl = pY + (size_t)l*TB*HID;
        zero_k<<<64, 256>>>(pC, BB*HID);
        gemm_tc<<<dim3(G4/128, TB/128), 256>>>(Xin, Wih + (size_t)l*G4*HID,
                                               pXW, bih + l*G4, bhh + l*G4,
                                               G4, HID);
        for(int t = 0; t < TT; t++){
            const float* hp = (t == 0) ? pZ : (Yl + (size_t)(t-1)*BB*HID);
            float *hT = nullptr, *cT = nullptr;
            if(t == TT-1){
                hT = out + LOGITS + (size_t)l*BB*HID;
                cT = out + LOGITS + (size_t)(2 + l)*BB*HID;
            }
            lstm_step<<<128, 256, STEP_SMEM>>>(hp, Whh + (size_t)l*G4*HID,
                                               pXW + (size_t)t*BB*G4, pC,
                                               Yl + (size_t)t*BB*HID, hT, cT);
        }
    }

    // tf32 tensor-core decoder GEMM: 2048 x 50257 x 1024
    gemm_tc<<<dim3((VOC + 127)/128, TB/128), 256>>>(pY + (size_t)TB*HID, decW,
                                                    out, decb, nullptr,
                                                    VOC, HID);

    logsoftmax_k<<<TB, 512>>>(out);
}

// round 8
// speedup vs baseline: 1.8767x; 1.2089x over previous
#include <cuda_runtime.h>
#include <cstdint>

#define TT   128
#define BB   16
#define HID  1024
#define G4   4096
#define VOC  50257
#define TB   (TT*BB)                 // 2048 rows
#define LOGITS ((size_t)TB*(size_t)VOC)

// ---------------- scratch (device globals; no allocation allowed) ----------
__device__ float g_emb[TB*HID];      // embedded input          8 MB
__device__ float g_Y[2*TB*HID];      // per-layer LSTM outputs 16 MB
__device__ float g_XW[TB*G4];        // input projections      32 MB
__device__ unsigned g_cnt;           // grid-barrier counter

// ---------------- packed f32x2 helpers --------------------------------------
__device__ __forceinline__ unsigned long long pk2(float a, float b){
    unsigned long long r;
    asm("mov.b64 %0, {%1, %2};" : "=l"(r) : "f"(a), "f"(b));
    return r;
}
__device__ __forceinline__ void upk2(unsigned long long v, float &a, float &b){
    asm("mov.b64 {%0, %1}, %2;" : "=f"(a), "=f"(b) : "l"(v));
}
__device__ __forceinline__ unsigned long long fma2(unsigned long long a,
                                                   unsigned long long b,
                                                   unsigned long long c){
    unsigned long long d;
    asm("fma.rn.f32x2 %0, %1, %2, %3;" : "=l"(d) : "l"(a), "l"(b), "l"(c));
    return d;
}

// ---------------- tf32 / cp.async helpers -----------------------------------
__device__ __forceinline__ uint32_t f2t(float x){
    uint32_t u;
    asm("cvt.rna.tf32.f32 %0, %1;" : "=r"(u) : "f"(x));
    return u;
}
__device__ __forceinline__ void mma_tf32(float* c, const uint32_t* a,
                                         const uint32_t* b){
    asm volatile(
        "mma.sync.aligned.m16n8k8.row.col.f32.tf32.tf32.f32 "
        "{%0,%1,%2,%3}, {%4,%5,%6,%7}, {%8,%9}, {%0,%1,%2,%3};"
        : "+f"(c[0]), "+f"(c[1]), "+f"(c[2]), "+f"(c[3])
        : "r"(a[0]), "r"(a[1]), "r"(a[2]), "r"(a[3]), "r"(b[0]), "r"(b[1]));
}
__device__ __forceinline__ uint32_t smem_u32(const void* p){
    uint32_t a;
    asm("{ .reg .u64 t; cvta.to.shared.u64 t, %1; cvt.u32.u64 %0, t; }"
        : "=r"(a) : "l"(p));
    return a;
}
__device__ __forceinline__ void cpa16(uint32_t dst, const void* src, int sz){
    asm volatile("cp.async.cg.shared.global [%0], [%1], 16, %2;"
                 :: "r"(dst), "l"(src), "r"(sz) : "memory");
}

// ---------------- small utility kernels ------------------------------------
__global__ void reset_cnt(){ g_cnt = 0u; }

__global__ void embed_k(const int* __restrict__ tokens,
                        const float* __restrict__ embW,
                        float* __restrict__ X){
    int row = blockIdx.x;                    // row = t*16 + b
    int tok = tokens[row];
    const float4* src = (const float4*)(embW + (size_t)tok*HID);
    float4* dst = (float4*)(X + (size_t)row*HID);
    for(int i = threadIdx.x; i < HID/4; i += blockDim.x) dst[i] = src[i];
}

// ---------------- tf32 tensor-core GEMM, 2-stage cp.async pipeline ----------
// C[M,N] = A[M,K] * B[N,K]^T + b1[n] (+ b2[n]).  NT, both K-contiguous.
// BM=BN=128, BK=32, 256 thr = 8 warps (2M x 4N), warp tile 64x32 of m16n8k8.
#define TCP 36                       // padded smem row stride (floats)
#define STG_F (2*128*TCP)            // floats per stage (As + Bs)

__device__ __forceinline__ void g_issue(const float* A, const float* Bm,
                                        float* As, float* Bs,
                                        int bm, int bn, int kt, int N, int K,
                                        int lm, int lq0)
{
    uint32_t sA = smem_u32(As), sB = smem_u32(Bs);
#pragma unroll
    for(int h = 0; h < 4; h++){
        int q = lq0 + h;
        cpa16(sA + (uint32_t)(lm*TCP + q*4)*4,
              A + (size_t)(bm + lm)*K + kt + q*4, 16);
        int rowb = bn + lm;
        int ok = (rowb < N) ? 16 : 0;
        cpa16(sB + (uint32_t)(lm*TCP + q*4)*4,
              Bm + (size_t)(ok ? rowb : 0)*K + kt + q*4, ok);
    }
    asm volatile("cp.async.commit_group;" ::: "memory");
}

__global__ __launch_bounds__(256, 2)
void gemm_tc(const float* __restrict__ A, const float* __restrict__ Bm,
             float* __restrict__ C, const float* __restrict__ b1,
             const float* __restrict__ b2, int N, int K)
{
    extern __shared__ float smp[];
    const int tid = threadIdx.x;
    const int wid = tid >> 5, lane = tid & 31;
    const int r = lane >> 2, cc = lane & 3;
    const int wm = (wid & 1) * 64;
    const int wn = (wid >> 1) * 32;
    const int bm = blockIdx.y * 128, bn = blockIdx.x * 128;
    const int lm = tid >> 1;                // load row 0..127
    const int lq0 = (tid & 1) * 4;          // float4 slot base: 0 or 4

    float acc[4][4][4];
#pragma unroll
    for(int mi=0;mi<4;mi++)
#pragma unroll
        for(int ni=0;ni<4;ni++)
#pragma unroll
            for(int q=0;q<4;q++) acc[mi][ni][q] = 0.f;

    const int nkt = K >> 5;
    g_issue(A, Bm, smp, smp + 128*TCP, bm, bn, 0, N, K, lm, lq0);

    for(int it = 0; it < nkt; it++){
        int s = it & 1;
        if(it + 1 < nkt){
            float* As1 = smp + (s^1)*STG_F;
            g_issue(A, Bm, As1, As1 + 128*TCP, bm, bn, (it+1)*32, N, K, lm, lq0);
            asm volatile("cp.async.wait_group 1;" ::: "memory");
        } else {
            asm volatile("cp.async.wait_group 0;" ::: "memory");
        }
        __syncthreads();

        const float* As = smp + s*STG_F;
        const float* Bs = As + 128*TCP;
#pragma unroll
        for(int ks = 0; ks < 4; ks++){
            const int k0 = ks*8;
            uint32_t af[4][4], bf[4][2];
#pragma unroll
            for(int mi=0;mi<4;mi++){
                const float* ap = As + (wm + mi*16 + r)*TCP + k0 + cc;
                af[mi][0] = f2t(ap[0]);
                af[mi][1] = f2t(ap[8*TCP]);
                af[mi][2] = f2t(ap[4]);
                af[mi][3] = f2t(ap[8*TCP + 4]);
            }
#pragma unroll
            for(int ni=0;ni<4;ni++){
                const float* bp = Bs + (wn + ni*8 + r)*TCP + k0 + cc;
                bf[ni][0] = f2t(bp[0]);
                bf[ni][1] = f2t(bp[4]);
            }
#pragma unroll
            for(int mi=0;mi<4;mi++)
#pragma unroll
                for(int ni=0;ni<4;ni++)
                    mma_tf32(acc[mi][ni], af[mi], bf[ni]);
        }
        __syncthreads();
    }

    // epilogue
#pragma unroll
    for(int ni=0;ni<4;ni++){
        int col = bn + wn + ni*8 + 2*cc;
        if(col >= N) continue;
        bool c1ok = (col + 1 < N);
        float bb0 = b1[col] + (b2 ? b2[col] : 0.f);
        float bb1 = c1ok ? (b1[col+1] + (b2 ? b2[col+1] : 0.f)) : 0.f;
#pragma unroll
        for(int mi=0;mi<4;mi++){
            size_t row0 = (size_t)(bm + wm + mi*16 + r);
            float* p0 = C + row0*(size_t)N + col;
            float* p1 = C + (row0+8)*(size_t)N + col;
            p0[0] = acc[mi][ni][0] + bb0;
            if(c1ok) p0[1] = acc[mi][ni][1] + bb1;
            p1[0] = acc[mi][ni][2] + bb0;
            if(c1ok) p1[1] = acc[mi][ni][3] + bb1;
        }
    }
}

// ---------------- persistent LSTM layer kernel ------------------------------
// One launch runs all 128 timesteps of one layer. 128 blocks (one per SM,
// co-resident), 256 threads. Whh rows for this block cached in SMEM once;
// cell state in registers; grid-wide barrier (monotonic counter) per step.
// smem: w_s 32*1024 f | h_s 16*1024 f | gates 512 f  => 198656 B
#define LSTM_SMEM ((32*HID + BB*HID + 512)*4)

__global__ __launch_bounds__(256, 1)
void lstm_seq(const float* __restrict__ Whh_l,
              const float* __restrict__ XW,
              float* __restrict__ Y,
              float* __restrict__ hT,
              float* __restrict__ cT)
{
    extern __shared__ float sm[];
    float* w_s   = sm;                  // 32 rows x 1024
    float* h_s   = sm + 32*HID;         // 16 x 1024
    float* gates = h_s + BB*HID;        // 512

    const int tid = threadIdx.x;
    const int w = tid >> 5, lane = tid & 31;
    const int g = w >> 1, rbase = (w & 1)*4;
    const int ub = blockIdx.x*8;
    const int NB = gridDim.x;

    // ---- stage this block's 32 Whh rows into smem (once) ----
    {
        const int row4 = HID/4;         // float4 per row
        for(int i = tid; i < 32*row4; i += 256){
            int rowloc = i / row4, c4 = i % row4;
            int gg = rowloc >> 3, rr = rowloc & 7;
            ((float4*)w_s)[i] =
                ((const float4*)(Whh_l + (size_t)(gg*HID + ub + rr)*HID))[c4];
        }
    }

    // cell state in registers (threads 0..127 own one (unit, batch) cell)
    float creg = 0.f;
    const int ul = (tid < 128) ? (tid >> 4) : 0;
    const int bb = (tid < 128) ? (tid & 15) : 0;

    __syncthreads();

    for(int t = 0; t < TT; t++){
        // ---- stage h_prev ----
        if(t == 0){
            float4 z = make_float4(0.f,0.f,0.f,0.f);
            for(int i = tid; i < BB*HID/4; i += 256) ((float4*)h_s)[i] = z;
        } else {
            const float4* src = (const float4*)(Y + (size_t)(t-1)*BB*HID);
            for(int i = tid; i < BB*HID/4; i += 256)
                ((float4*)h_s)[i] = __ldcg(src + i);
        }
        __syncthreads();

        // ---- 4 gate-rows x 16 batches dot products per warp ----
        unsigned long long acc[4][8];
#pragma unroll
        for(int jj=0;jj<4;jj++)
#pragma unroll
            for(int p=0;p<8;p++) acc[jj][p] = 0ull;

        const float* wr0 = w_s + (size_t)(g*8 + rbase)*HID;
        for(int c = 0; c < 32; c++){
            int k = c*32 + lane;
            unsigned long long hp[8];
#pragma unroll
            for(int p=0;p<8;p++)
                hp[p] = pk2(h_s[(2*p)*HID + k], h_s[(2*p+1)*HID + k]);
#pragma unroll
            for(int jj=0;jj<4;jj++){
                float wv = wr0[jj*HID + k];
                unsigned long long wd = pk2(wv, wv);
#pragma unroll
                for(int p=0;p<8;p++) acc[jj][p] = fma2(wd, hp[p], acc[jj][p]);
            }
        }

        float red[4][16];
#pragma unroll
        for(int jj=0;jj<4;jj++)
#pragma unroll
            for(int p=0;p<8;p++) upk2(acc[jj][p], red[jj][2*p], red[jj][2*p+1]);
#pragma unroll
        for(int jj=0;jj<4;jj++)
#pragma unroll
            for(int b=0;b<16;b++)
#pragma unroll
                for(int o=16;o>0;o>>=1)
                    red[jj][b] += __shfl_xor_sync(0xffffffffu, red[jj][b], o);

        const float* XWt = XW + (size_t)t*BB*G4;
        if(lane < 16){
#pragma unroll
            for(int jj=0;jj<4;jj++){
                int rloc = rbase + jj;
                float gate = red[jj][lane] +
                             __ldcg(XWt + (size_t)lane*G4 + g*HID + ub + rloc);
                gates[(g*8 + rloc)*16 + lane] = gate;
            }
        }
        __syncthreads();

        // ---- cell update ----
        if(tid < 128){
            float iv = gates[(0*8+ul)*16 + bb];
            float fv = gates[(1*8+ul)*16 + bb];
            float gv = gates[(2*8+ul)*16 + bb];
            float ov = gates[(3*8+ul)*16 + bb];
            iv = 1.f/(1.f + __expf(-iv));
            fv = 1.f/(1.f + __expf(-fv));
            ov = 1.f/(1.f + __expf(-ov));
            gv = tanhf(gv);
            float cn = fv*creg + iv*gv;
            float hn = ov*tanhf(cn);
            creg = cn;
            int u = ub + ul;
            Y[(size_t)t*BB*HID + bb*HID + u] = hn;
            if(t == TT-1){
                hT[bb*HID + u] = hn;
                cT[bb*HID + u] = cn;
            }
        }

        // ---- grid barrier (release h writes of step t) ----
        __syncthreads();
        if(tid == 0){
            __threadfence();
            atomicAdd(&g_cnt, 1u);
            unsigned target = (unsigned)(t + 1) * (unsigned)NB;
            while(*(volatile unsigned*)&g_cnt < target) {}
            __threadfence();
        }
        __syncthreads();
    }
}

// ---------------- row-wise log_softmax over 50257, in place -----------------
__global__ void logsoftmax_k(float* __restrict__ p0){
    __shared__ float red[33];
    int row = blockIdx.x;
    float* p = p0 + (size_t)row*(size_t)VOC;
    int tid = threadIdx.x, lane = tid & 31, w = tid >> 5;
    int nthr = blockDim.x, nw = nthr >> 5;

    float m = -3.4e38f;
    for(int i = tid; i < VOC; i += nthr) m = fmaxf(m, p[i]);
#pragma unroll
    for(int o=16;o>0;o>>=1) m = fmaxf(m, __shfl_xor_sync(0xffffffffu, m, o));
    if(lane == 0) red[w] = m;
    __syncthreads();
    if(tid == 0){
        float mm = red[0];
        for(int i=1;i<nw;i++) mm = fmaxf(mm, red[i]);
        red[32] = mm;
    }
    __syncthreads();
    float M = red[32];

    float s = 0.f;
    for(int i = tid; i < VOC; i += nthr) s += __expf(p[i] - M);
#pragma unroll
    for(int o=16;o>0;o>>=1) s += __shfl_xor_sync(0xffffffffu, s, o);
    __syncthreads();
    if(lane == 0) red[w] = s;
    __syncthreads();
    if(tid == 0){
        float ss = 0.f;
        for(int i=0;i<nw;i++) ss += red[i];
        red[32] = M + logf(ss);
    }
    __syncthreads();
    float lse = red[32];
    for(int i = tid; i < VOC; i += nthr) p[i] -= lse;
}

// ---------------- launcher ---------------------------------------------------
extern "C" void kernel_launch(void* const* d_in, const int* in_sizes, int n_in,
                              void* d_out, int out_size)
{
    const int*   tokens = (const int*)  d_in[0];
    const float* embW   = (const float*)d_in[1];
    const float* Wih    = (const float*)d_in[2];
    const float* Whh    = (const float*)d_in[3];
    const float* bih    = (const float*)d_in[4];
    const float* bhh    = (const float*)d_in[5];
    const float* decW   = (const float*)d_in[6];
    const float* decb   = (const float*)d_in[7];
    float* out = (float*)d_out;

    float *pEmb,*pY,*pXW;
    cudaGetSymbolAddress((void**)&pEmb, g_emb);
    cudaGetSymbolAddress((void**)&pY,   g_Y);
    cudaGetSymbolAddress((void**)&pXW,  g_XW);

    const int GEMM_SMEM = 2*STG_F*4;             // 73728 B
    cudaFuncSetAttribute(gemm_tc, cudaFuncAttributeMaxDynamicSharedMemorySize,
                         GEMM_SMEM);
    cudaFuncSetAttribute(lstm_seq, cudaFuncAttributeMaxDynamicSharedMemorySize,
                         LSTM_SMEM);

    embed_k<<<TB, 256>>>(tokens, embW, pEmb);

    for(int l = 0; l < 2; l++){
        const float* Xin = (l == 0) ? pEmb : pY;          // layer0 out at pY
        float* Yl = pY + (size_t)l*TB*HID;
        gemm_tc<<<dim3(G4/128, TB/128), 256, GEMM_SMEM>>>(
            Xin, Wih + (size_t)l*G4*HID, pXW,
            bih + l*G4, bhh + l*G4, G4, HID);
        reset_cnt<<<1, 1>>>();
        lstm_seq<<<128, 256, LSTM_SMEM>>>(
            Whh + (size_t)l*G4*HID, pXW, Yl,
            out + LOGITS + (size_t)l*BB*HID,
            out + LOGITS + (size_t)(2 + l)*BB*HID);
    }

    // tf32 tensor-core decoder GEMM: 2048 x 50257 x 1024
    gemm_tc<<<dim3((VOC + 127)/128, TB/128), 256, GEMM_SMEM>>>(
        pY + (size_t)TB*HID, decW, out, decb, nullptr, VOC, HID);

    logsoftmax_k<<<TB, 512>>>(out);
}

// round 9
// speedup vs baseline: 2.3590x; 1.2570x over previous
#include <cuda_runtime.h>
#include <cstdint>

#define TT   128
#define BB   16
#define HID  1024
#define G4   4096
#define VOC  50257
#define TB   (TT*BB)                 // 2048 rows
#define LOGITS ((size_t)TB*(size_t)VOC)

// ---------------- scratch (device globals; no allocation allowed) ----------
__device__ float g_emb[TB*HID];      // embedded input          8 MB
__device__ float g_Y[2*TB*HID];      // per-layer LSTM outputs 16 MB
__device__ float g_XW[TB*G4];        // input projections      32 MB
__device__ unsigned g_cnt;           // grid-barrier counter

// ---------------- tf32 / cp.async helpers -----------------------------------
__device__ __forceinline__ uint32_t f2t(float x){
    uint32_t u;
    asm("cvt.rna.tf32.f32 %0, %1;" : "=r"(u) : "f"(x));
    return u;
}
// split fp32 into tf32 hi + tf32 lo (hi+lo ~ exact)
__device__ __forceinline__ void tsplit(float x, uint32_t& hi, uint32_t& lo){
    hi = f2t(x);
    lo = f2t(x - __uint_as_float(hi));
}
__device__ __forceinline__ void mma_tf32(float* c, const uint32_t* a,
                                         const uint32_t* b){
    asm volatile(
        "mma.sync.aligned.m16n8k8.row.col.f32.tf32.tf32.f32 "
        "{%0,%1,%2,%3}, {%4,%5,%6,%7}, {%8,%9}, {%0,%1,%2,%3};"
        : "+f"(c[0]), "+f"(c[1]), "+f"(c[2]), "+f"(c[3])
        : "r"(a[0]), "r"(a[1]), "r"(a[2]), "r"(a[3]), "r"(b[0]), "r"(b[1]));
}
__device__ __forceinline__ uint32_t smem_u32(const void* p){
    uint32_t a;
    asm("{ .reg .u64 t; cvta.to.shared.u64 t, %1; cvt.u32.u64 %0, t; }"
        : "=r"(a) : "l"(p));
    return a;
}
__device__ __forceinline__ void cpa16(uint32_t dst, const void* src, int sz){
    asm volatile("cp.async.cg.shared.global [%0], [%1], 16, %2;"
                 :: "r"(dst), "l"(src), "r"(sz) : "memory");
}

// ---------------- small utility kernels ------------------------------------
__global__ void reset_cnt(){ g_cnt = 0u; }

__global__ void embed_k(const int* __restrict__ tokens,
                        const float* __restrict__ embW,
                        float* __restrict__ X){
    int row = blockIdx.x;                    // row = t*16 + b
    int tok = tokens[row];
    const float4* src = (const float4*)(embW + (size_t)tok*HID);
    float4* dst = (float4*)(X + (size_t)row*HID);
    for(int i = threadIdx.x; i < HID/4; i += blockDim.x) dst[i] = src[i];
}

// ---------------- tf32 tensor-core GEMM, 2-stage cp.async pipeline ----------
// C[M,N] = A[M,K] * B[N,K]^T + b1[n] (+ b2[n]).  NT, both K-contiguous.
#define TCP 36                       // padded smem row stride (floats)
#define STG_F (2*128*TCP)            // floats per stage (As + Bs)

__device__ __forceinline__ void g_issue(const float* A, const float* Bm,
                                        float* As, float* Bs,
                                        int bm, int bn, int kt, int N, int K,
                                        int lm, int lq0)
{
    uint32_t sA = smem_u32(As), sB = smem_u32(Bs);
#pragma unroll
    for(int h = 0; h < 4; h++){
        int q = lq0 + h;
        cpa16(sA + (uint32_t)(lm*TCP + q*4)*4,
              A + (size_t)(bm + lm)*K + kt + q*4, 16);
        int rowb = bn + lm;
        int ok = (rowb < N) ? 16 : 0;
        cpa16(sB + (uint32_t)(lm*TCP + q*4)*4,
              Bm + (size_t)(ok ? rowb : 0)*K + kt + q*4, ok);
    }
    asm volatile("cp.async.commit_group;" ::: "memory");
}

__global__ __launch_bounds__(256, 2)
void gemm_tc(const float* __restrict__ A, const float* __restrict__ Bm,
             float* __restrict__ C, const float* __restrict__ b1,
             const float* __restrict__ b2, int N, int K)
{
    extern __shared__ float smp[];
    const int tid = threadIdx.x;
    const int wid = tid >> 5, lane = tid & 31;
    const int r = lane >> 2, cc = lane & 3;
    const int wm = (wid & 1) * 64;
    const int wn = (wid >> 1) * 32;
    const int bm = blockIdx.y * 128, bn = blockIdx.x * 128;
    const int lm = tid >> 1;
    const int lq0 = (tid & 1) * 4;

    float acc[4][4][4];
#pragma unroll
    for(int mi=0;mi<4;mi++)
#pragma unroll
        for(int ni=0;ni<4;ni++)
#pragma unroll
            for(int q=0;q<4;q++) acc[mi][ni][q] = 0.f;

    const int nkt = K >> 5;
    g_issue(A, Bm, smp, smp + 128*TCP, bm, bn, 0, N, K, lm, lq0);

    for(int it = 0; it < nkt; it++){
        int s = it & 1;
        if(it + 1 < nkt){
            float* As1 = smp + (s^1)*STG_F;
            g_issue(A, Bm, As1, As1 + 128*TCP, bm, bn, (it+1)*32, N, K, lm, lq0);
            asm volatile("cp.async.wait_group 1;" ::: "memory");
        } else {
            asm volatile("cp.async.wait_group 0;" ::: "memory");
        }
        __syncthreads();

        const float* As = smp + s*STG_F;
        const float* Bs = As + 128*TCP;
#pragma unroll
        for(int ks = 0; ks < 4; ks++){
            const int k0 = ks*8;
            uint32_t af[4][4], bf[4][2];
#pragma unroll
            for(int mi=0;mi<4;mi++){
                const float* ap = As + (wm + mi*16 + r)*TCP + k0 + cc;
                af[mi][0] = f2t(ap[0]);
                af[mi][1] = f2t(ap[8*TCP]);
                af[mi][2] = f2t(ap[4]);
                af[mi][3] = f2t(ap[8*TCP + 4]);
            }
#pragma unroll
            for(int ni=0;ni<4;ni++){
                const float* bp = Bs + (wn + ni*8 + r)*TCP + k0 + cc;
                bf[ni][0] = f2t(bp[0]);
                bf[ni][1] = f2t(bp[4]);
            }
#pragma unroll
            for(int mi=0;mi<4;mi++)
#pragma unroll
                for(int ni=0;ni<4;ni++)
                    mma_tf32(acc[mi][ni], af[mi], bf[ni]);
        }
        __syncthreads();
    }

#pragma unroll
    for(int ni=0;ni<4;ni++){
        int col = bn + wn + ni*8 + 2*cc;
        if(col >= N) continue;
        bool c1ok = (col + 1 < N);
        float bb0 = b1[col] + (b2 ? b2[col] : 0.f);
        float bb1 = c1ok ? (b1[col+1] + (b2 ? b2[col+1] : 0.f)) : 0.f;
#pragma unroll
        for(int mi=0;mi<4;mi++){
            size_t row0 = (size_t)(bm + wm + mi*16 + r);
            float* p0 = C + row0*(size_t)N + col;
            float* p1 = C + (row0+8)*(size_t)N + col;
            p0[0] = acc[mi][ni][0] + bb0;
            if(c1ok) p0[1] = acc[mi][ni][1] + bb1;
            p1[0] = acc[mi][ni][2] + bb0;
            if(c1ok) p1[1] = acc[mi][ni][3] + bb1;
        }
    }
}

// ---------------- persistent LSTM layer, tensor-core recurrence -------------
// 128 blocks (co-resident), 256 threads. Per block: 8 hidden units = 32 gate
// rows. Per step: gates[16,32] = h[16,1024] @ W[32,1024]^T via m16n8k8 tf32
// mma, K split over 8 warps (128 each), partials reduced through SMEM.
// W pre-truncated to tf32 in SMEM once; h split hi/lo in registers (2 MMAs)
// so only W carries tf32 error. Cell state in registers. Grid barrier/step.
#define WS_STR 1028                          // smem row stride (floats)
#define LSTM_SMEM ((32*WS_STR + 16*WS_STR + 8*528 + 512)*4)   // 216320 B

__global__ __launch_bounds__(256, 1)
void lstm_seq(const float* __restrict__ Whh_l,
              const float* __restrict__ XW,
              float* __restrict__ Y,
              float* __restrict__ hT,
              float* __restrict__ cT)
{
    extern __shared__ float sm[];
    float* w_s   = sm;                       // 32 x WS_STR (tf32-as-f32)
    float* h_s   = sm + 32*WS_STR;           // 16 x WS_STR (fp32)
    float* part  = h_s + 16*WS_STR;          // 8 warps x (16 x 33)
    float* gates = part + 8*528;             // 32 x 16

    const int tid = threadIdx.x;
    const int w = tid >> 5, lane = tid & 31;
    const int r = lane >> 2, cc = lane & 3;
    const int ub = blockIdx.x*8;
    const int NB = gridDim.x;

    // ---- stage + tf32-truncate this block's 32 Whh rows (once) ----
    {
        const int row4 = HID/4;
        for(int i = tid; i < 32*row4; i += 256){
            int row = i / row4, c4 = i % row4;
            int gg = row >> 3, rr = row & 7;
            float4 v = ((const float4*)(Whh_l + (size_t)(gg*HID + ub + rr)*HID))[c4];
            float* dst = w_s + row*WS_STR + c4*4;
            dst[0] = __uint_as_float(f2t(v.x));
            dst[1] = __uint_as_float(f2t(v.y));
            dst[2] = __uint_as_float(f2t(v.z));
            dst[3] = __uint_as_float(f2t(v.w));
        }
    }

    float creg = 0.f;
    const int ul = tid >> 4, bb2 = tid & 15;     // cell-update mapping (tid<128)
    __syncthreads();

    for(int t = 0; t < TT; t++){
        // ---- stage h_prev (fp32) ----
        if(t == 0){
            float4 z = make_float4(0.f,0.f,0.f,0.f);
            for(int i = tid; i < BB*(HID/4); i += 256){
                int b = i / (HID/4), c4 = i % (HID/4);
                *(float4*)(h_s + b*WS_STR + c4*4) = z;
            }
        } else {
            const float4* src = (const float4*)(Y + (size_t)(t-1)*BB*HID);
            for(int i = tid; i < BB*(HID/4); i += 256){
                int b = i / (HID/4), c4 = i % (HID/4);
                *(float4*)(h_s + b*WS_STR + c4*4) = __ldcg(src + i);
            }
        }
        __syncthreads();

        // ---- prefetch XW for my 2 gate cells ----
        const float* XWt = XW + (size_t)t*BB*G4;
        const int c0 = tid, c1 = tid + 256;      // cell = b*32 + n
        float xw0 = __ldcg(XWt + (size_t)(c0 >> 5)*G4
                           + ((c0 & 31) >> 3)*HID + ub + (c0 & 7));
        float xw1 = __ldcg(XWt + (size_t)(c1 >> 5)*G4
                           + ((c1 & 31) >> 3)*HID + ub + (c1 & 7));

        // ---- mma over this warp's K slice ----
        float acc[4][4];
#pragma unroll
        for(int ni=0;ni<4;ni++)
#pragma unroll
            for(int q=0;q<4;q++) acc[ni][q] = 0.f;

        const int kbase = w*128;
#pragma unroll 4
        for(int kk = 0; kk < 16; kk++){
            int k = kbase + kk*8;
            uint32_t ah[4], al[4];
            tsplit(h_s[ r     *WS_STR + k + cc],     ah[0], al[0]);
            tsplit(h_s[(r + 8)*WS_STR + k + cc],     ah[1], al[1]);
            tsplit(h_s[ r     *WS_STR + k + 4 + cc], ah[2], al[2]);
            tsplit(h_s[(r + 8)*WS_STR + k + 4 + cc], ah[3], al[3]);
            uint32_t bf[4][2];
#pragma unroll
            for(int ni=0;ni<4;ni++){
                bf[ni][0] = __float_as_uint(w_s[(ni*8 + r)*WS_STR + k + cc]);
                bf[ni][1] = __float_as_uint(w_s[(ni*8 + r)*WS_STR + k + 4 + cc]);
            }
#pragma unroll
            for(int ni=0;ni<4;ni++){
                mma_tf32(acc[ni], ah, bf[ni]);
                mma_tf32(acc[ni], al, bf[ni]);
            }
        }

        // ---- write partials: part[w][b][n] (stride 33) ----
#pragma unroll
        for(int ni=0;ni<4;ni++){
            int n0 = ni*8 + 2*cc;
            part[w*528 +  r     *33 + n0    ] = acc[ni][0];
            part[w*528 +  r     *33 + n0 + 1] = acc[ni][1];
            part[w*528 + (r + 8)*33 + n0    ] = acc[ni][2];
            part[w*528 + (r + 8)*33 + n0 + 1] = acc[ni][3];
        }
        __syncthreads();

        // ---- reduce 8 partials + XW -> gates[n][b] ----
        {
            int b0 = c0 >> 5, n0 = c0 & 31;
            int b1 = c1 >> 5, n1 = c1 & 31;
            float s0 = xw0, s1 = xw1;
#pragma unroll
            for(int ww = 0; ww < 8; ww++){
                s0 += part[ww*528 + b0*33 + n0];
                s1 += part[ww*528 + b1*33 + n1];
            }
            gates[n0*16 + b0] = s0;
            gates[n1*16 + b1] = s1;
        }
        __syncthreads();

        // ---- cell update (threads 0..127 own one (unit, batch)) ----
        if(tid < 128){
            float iv = gates[(0*8 + ul)*16 + bb2];
            float fv = gates[(1*8 + ul)*16 + bb2];
            float gv = gates[(2*8 + ul)*16 + bb2];
            float ov = gates[(3*8 + ul)*16 + bb2];
            iv = 1.f/(1.f + __expf(-iv));
            fv = 1.f/(1.f + __expf(-fv));
            ov = 1.f/(1.f + __expf(-ov));
            gv = tanhf(gv);
            float cn = fv*creg + iv*gv;
            float hn = ov*tanhf(cn);
            creg = cn;
            int u = ub + ul;
            Y[(size_t)t*BB*HID + bb2*HID + u] = hn;
            if(t == TT-1){
                hT[bb2*HID + u] = hn;
                cT[bb2*HID + u] = cn;
            }
        }

        // ---- grid barrier (release Y writes of step t) ----
        __syncthreads();
        if(tid == 0){
            __threadfence();
            atomicAdd(&g_cnt, 1u);
            unsigned target = (unsigned)(t + 1) * (unsigned)NB;
            while(*(volatile unsigned*)&g_cnt < target) {}
            __threadfence();
        }
        __syncthreads();
    }
}

// ---------------- row-wise log_softmax over 50257, in place -----------------
__global__ void logsoftmax_k(float* __restrict__ p0){
    __shared__ float red[33];
    int row = blockIdx.x;
    float* p = p0 + (size_t)row*(size_t)VOC;
    int tid = threadIdx.x, lane = tid & 31, w = tid >> 5;
    int nthr = blockDim.x, nw = nthr >> 5;

    float m = -3.4e38f;
    for(int i = tid; i < VOC; i += nthr) m = fmaxf(m, p[i]);
#pragma unroll
    for(int o=16;o>0;o>>=1) m = fmaxf(m, __shfl_xor_sync(0xffffffffu, m, o));
    if(lane == 0) red[w] = m;
    __syncthreads();
    if(tid == 0){
        float mm = red[0];
        for(int i=1;i<nw;i++) mm = fmaxf(mm, red[i]);
        red[32] = mm;
    }
    __syncthreads();
    float M = red[32];

    float s = 0.f;
    for(int i = tid; i < VOC; i += nthr) s += __expf(p[i] - M);
#pragma unroll
    for(int o=16;o>0;o>>=1) s += __shfl_xor_sync(0xffffffffu, s, o);
    __syncthreads();
    if(lane == 0) red[w] = s;
    __syncthreads();
    if(tid == 0){
        float ss = 0.f;
        for(int i=0;i<nw;i++) ss += red[i];
        red[32] = M + logf(ss);
    }
    __syncthreads();
    float lse = red[32];
    for(int i = tid; i < VOC; i += nthr) p[i] -= lse;
}

// ---------------- launcher ---------------------------------------------------
extern "C" void kernel_launch(void* const* d_in, const int* in_sizes, int n_in,
                              void* d_out, int out_size)
{
    const int*   tokens = (const int*)  d_in[0];
    const float* embW   = (const float*)d_in[1];
    const float* Wih    = (const float*)d_in[2];
    const float* Whh    = (const float*)d_in[3];
    const float* bih    = (const float*)d_in[4];
    const float* bhh    = (const float*)d_in[5];
    const float* decW   = (const float*)d_in[6];
    const float* decb   = (const float*)d_in[7];
    float* out = (float*)d_out;

    float *pEmb,*pY,*pXW;
    cudaGetSymbolAddress((void**)&pEmb, g_emb);
    cudaGetSymbolAddress((void**)&pY,   g_Y);
    cudaGetSymbolAddress((void**)&pXW,  g_XW);

    const int GEMM_SMEM = 2*STG_F*4;             // 73728 B
    cudaFuncSetAttribute(gemm_tc, cudaFuncAttributeMaxDynamicSharedMemorySize,
                         GEMM_SMEM);
    cudaFuncSetAttribute(lstm_seq, cudaFuncAttributeMaxDynamicSharedMemorySize,
                         LSTM_SMEM);

    embed_k<<<TB, 256>>>(tokens, embW, pEmb);

    for(int l = 0; l < 2; l++){
        const float* Xin = (l == 0) ? pEmb : pY;          // layer0 out at pY
        float* Yl = pY + (size_t)l*TB*HID;
        gemm_tc<<<dim3(G4/128, TB/128), 256, GEMM_SMEM>>>(
            Xin, Wih + (size_t)l*G4*HID, pXW,
            bih + l*G4, bhh + l*G4, G4, HID);
        reset_cnt<<<1, 1>>>();
        lstm_seq<<<128, 256, LSTM_SMEM>>>(
            Whh + (size_t)l*G4*HID, pXW, Yl,
            out + LOGITS + (size_t)l*BB*HID,
            out + LOGITS + (size_t)(2 + l)*BB*HID);
    }

    // tf32 tensor-core decoder GEMM: 2048 x 50257 x 1024
    gemm_tc<<<dim3((VOC + 127)/128, TB/128), 256, GEMM_SMEM>>>(
        pY + (size_t)TB*HID, decW, out, decb, nullptr, VOC, HID);

    logsoftmax_k<<<TB, 512>>>(out);
}

// round 10
// speedup vs baseline: 2.3593x; 1.0002x over previous
#include <cuda_runtime.h>
#include <cstdint>

#define TT   128
#define BB   16
#define HID  1024
#define G4   4096
#define VOC  50257
#define TB   (TT*BB)                 // 2048 rows
#define LOGITS ((size_t)TB*(size_t)VOC)

// ---------------- scratch (device globals; no allocation allowed) ----------
__device__ float g_emb[TB*HID];      // embedded input          8 MB
__device__ float g_Y[2*TB*HID];      // per-layer LSTM outputs 16 MB
__device__ float g_XW[TB*G4];        // input projections      32 MB
__device__ unsigned g_cnt;           // grid-barrier counter

// ---------------- tf32 / cp.async helpers -----------------------------------
__device__ __forceinline__ uint32_t f2t(float x){
    uint32_t u;
    asm("cvt.rna.tf32.f32 %0, %1;" : "=r"(u) : "f"(x));
    return u;
}
// split fp32 into tf32 hi + tf32 lo (hi+lo ~ exact)
__device__ __forceinline__ void tsplit(float x, uint32_t& hi, uint32_t& lo){
    hi = f2t(x);
    lo = f2t(x - __uint_as_float(hi));
}
__device__ __forceinline__ void mma_tf32(float* c, const uint32_t* a,
                                         const uint32_t* b){
    asm volatile(
        "mma.sync.aligned.m16n8k8.row.col.f32.tf32.tf32.f32 "
        "{%0,%1,%2,%3}, {%4,%5,%6,%7}, {%8,%9}, {%0,%1,%2,%3};"
        : "+f"(c[0]), "+f"(c[1]), "+f"(c[2]), "+f"(c[3])
        : "r"(a[0]), "r"(a[1]), "r"(a[2]), "r"(a[3]), "r"(b[0]), "r"(b[1]));
}
__device__ __forceinline__ uint32_t smem_u32(const void* p){
    uint32_t a;
    asm("{ .reg .u64 t; cvta.to.shared.u64 t, %1; cvt.u32.u64 %0, t; }"
        : "=r"(a) : "l"(p));
    return a;
}
__device__ __forceinline__ void cpa16(uint32_t dst, const void* src, int sz){
    asm volatile("cp.async.cg.shared.global [%0], [%1], 16, %2;"
                 :: "r"(dst), "l"(src), "r"(sz) : "memory");
}

// ---------------- small utility kernels ------------------------------------
__global__ void reset_cnt(){ g_cnt = 0u; }

__global__ void embed_k(const int* __restrict__ tokens,
                        const float* __restrict__ embW,
                        float* __restrict__ X){
    int row = blockIdx.x;                    // row = t*16 + b
    int tok = tokens[row];
    const float4* src = (const float4*)(embW + (size_t)tok*HID);
    float4* dst = (float4*)(X + (size_t)row*HID);
    for(int i = threadIdx.x; i < HID/4; i += blockDim.x) dst[i] = src[i];
}

// ---------------- tf32 tensor-core GEMM, 3-stage cp.async pipeline ----------
// C[M,N] = A[M,K] * B[N,K]^T + b1[n] (+ b2[n]).  NT, both K-contiguous.
#define TCP 36                       // padded smem row stride (floats)
#define STG_F (2*128*TCP)            // floats per stage (As + Bs)
#define NSTG 3

__device__ __forceinline__ void g_issue(const float* A, const float* Bm,
                                        float* As, float* Bs,
                                        int bm, int bn, int kt, int N, int K,
                                        int lm, int lq0)
{
    uint32_t sA = smem_u32(As), sB = smem_u32(Bs);
#pragma unroll
    for(int h = 0; h < 4; h++){
        int q = lq0 + h;
        cpa16(sA + (uint32_t)(lm*TCP + q*4)*4,
              A + (size_t)(bm + lm)*K + kt + q*4, 16);
        int rowb = bn + lm;
        int ok = (rowb < N) ? 16 : 0;
        cpa16(sB + (uint32_t)(lm*TCP + q*4)*4,
              Bm + (size_t)(ok ? rowb : 0)*K + kt + q*4, ok);
    }
    asm volatile("cp.async.commit_group;" ::: "memory");
}

__global__ __launch_bounds__(256, 2)
void gemm_tc(const float* __restrict__ A, const float* __restrict__ Bm,
             float* __restrict__ C, const float* __restrict__ b1,
             const float* __restrict__ b2, int N, int K)
{
    extern __shared__ float smp[];
    const int tid = threadIdx.x;
    const int wid = tid >> 5, lane = tid & 31;
    const int r = lane >> 2, cc = lane & 3;
    const int wm = (wid & 1) * 64;
    const int wn = (wid >> 1) * 32;
    const int bm = blockIdx.y * 128, bn = blockIdx.x * 128;
    const int lm = tid >> 1;
    const int lq0 = (tid & 1) * 4;

    float acc[4][4][4];
#pragma unroll
    for(int mi=0;mi<4;mi++)
#pragma unroll
        for(int ni=0;ni<4;ni++)
#pragma unroll
            for(int q=0;q<4;q++) acc[mi][ni][q] = 0.f;

    const int nkt = K >> 5;
    g_issue(A, Bm, smp, smp + 128*TCP, bm, bn, 0, N, K, lm, lq0);
    if(nkt > 1){
        float* S1 = smp + STG_F;
        g_issue(A, Bm, S1, S1 + 128*TCP, bm, bn, 32, N, K, lm, lq0);
    }

    for(int it = 0; it < nkt; it++){
        int s = it % NSTG;
        if(it + 2 < nkt){
            float* Sn = smp + ((it+2) % NSTG)*STG_F;
            g_issue(A, Bm, Sn, Sn + 128*TCP, bm, bn, (it+2)*32, N, K, lm, lq0);
            asm volatile("cp.async.wait_group 2;" ::: "memory");
        } else if(it + 1 < nkt){
            asm volatile("cp.async.wait_group 1;" ::: "memory");
        } else {
            asm volatile("cp.async.wait_group 0;" ::: "memory");
        }
        __syncthreads();

        const float* As = smp + s*STG_F;
        const float* Bs = As + 128*TCP;
#pragma unroll
        for(int ks = 0; ks < 4; ks++){
            const int k0 = ks*8;
            uint32_t af[4][4], bf[4][2];
#pragma unroll
            for(int mi=0;mi<4;mi++){
                const float* ap = As + (wm + mi*16 + r)*TCP + k0 + cc;
                af[mi][0] = f2t(ap[0]);
                af[mi][1] = f2t(ap[8*TCP]);
                af[mi][2] = f2t(ap[4]);
                af[mi][3] = f2t(ap[8*TCP + 4]);
            }
#pragma unroll
            for(int ni=0;ni<4;ni++){
                const float* bp = Bs + (wn + ni*8 + r)*TCP + k0 + cc;
                bf[ni][0] = f2t(bp[0]);
                bf[ni][1] = f2t(bp[4]);
            }
#pragma unroll
            for(int mi=0;mi<4;mi++)
#pragma unroll
                for(int ni=0;ni<4;ni++)
                    mma_tf32(acc[mi][ni], af[mi], bf[ni]);
        }
        __syncthreads();
    }

#pragma unroll
    for(int ni=0;ni<4;ni++){
        int col = bn + wn + ni*8 + 2*cc;
        if(col >= N) continue;
        bool c1ok = (col + 1 < N);
        float bb0 = b1[col] + (b2 ? b2[col] : 0.f);
        float bb1 = c1ok ? (b1[col+1] + (b2 ? b2[col+1] : 0.f)) : 0.f;
#pragma unroll
        for(int mi=0;mi<4;mi++){
            size_t row0 = (size_t)(bm + wm + mi*16 + r);
            float* p0 = C + row0*(size_t)N + col;
            float* p1 = C + (row0+8)*(size_t)N + col;
            p0[0] = acc[mi][ni][0] + bb0;
            if(c1ok) p0[1] = acc[mi][ni][1] + bb1;
            p1[0] = acc[mi][ni][2] + bb0;
            if(c1ok) p1[1] = acc[mi][ni][3] + bb1;
        }
    }
}

// ---------------- persistent LSTM layer, tensor-core recurrence -------------
// 128 blocks (co-resident), 256 threads. Per block: 8 hidden units = 32 gate
// rows. Per step: gates[16,32] = h[16,1024] @ W[32,1024]^T via m16n8k8 tf32
// mma, K split over 8 warps (128 each), partials reduced through SMEM.
// W pre-truncated to tf32 in SMEM once; h split hi/lo with SEPARATE
// accumulators (halves the HMMA dependency chain). Grid barrier per step.
#define WS_STR 1028                          // smem row stride (floats)
#define LSTM_SMEM ((32*WS_STR + 16*WS_STR + 8*528 + 512)*4)   // 216320 B

__global__ __launch_bounds__(256, 1)
void lstm_seq(const float* __restrict__ Whh_l,
              const float* __restrict__ XW,
              float* __restrict__ Y,
              float* __restrict__ hT,
              float* __restrict__ cT)
{
    extern __shared__ float sm[];
    float* w_s   = sm;                       // 32 x WS_STR (tf32-as-f32)
    float* h_s   = sm + 32*WS_STR;           // 16 x WS_STR (fp32)
    float* part  = h_s + 16*WS_STR;          // 8 warps x (16 x 33)
    float* gates = part + 8*528;             // 32 x 16

    const int tid = threadIdx.x;
    const int w = tid >> 5, lane = tid & 31;
    const int r = lane >> 2, cc = lane & 3;
    const int ub = blockIdx.x*8;
    const int NB = gridDim.x;

    // ---- stage + tf32-truncate this block's 32 Whh rows (once) ----
    {
        const int row4 = HID/4;
        for(int i = tid; i < 32*row4; i += 256){
            int row = i / row4, c4 = i % row4;
            int gg = row >> 3, rr = row & 7;
            float4 v = ((const float4*)(Whh_l + (size_t)(gg*HID + ub + rr)*HID))[c4];
            float* dst = w_s + row*WS_STR + c4*4;
            dst[0] = __uint_as_float(f2t(v.x));
            dst[1] = __uint_as_float(f2t(v.y));
            dst[2] = __uint_as_float(f2t(v.z));
            dst[3] = __uint_as_float(f2t(v.w));
        }
    }

    float creg = 0.f;
    const int ul = tid >> 4, bb2 = tid & 15;     // cell-update mapping (tid<128)
    __syncthreads();

    for(int t = 0; t < TT; t++){
        // ---- stage h_prev (fp32) ----
        if(t == 0){
            float4 z = make_float4(0.f,0.f,0.f,0.f);
            for(int i = tid; i < BB*(HID/4); i += 256){
                int b = i / (HID/4), c4 = i % (HID/4);
                *(float4*)(h_s + b*WS_STR + c4*4) = z;
            }
        } else {
            const float4* src = (const float4*)(Y + (size_t)(t-1)*BB*HID);
            for(int i = tid; i < BB*(HID/4); i += 256){
                int b = i / (HID/4), c4 = i % (HID/4);
                *(float4*)(h_s + b*WS_STR + c4*4) = __ldcg(src + i);
            }
        }
        __syncthreads();

        // ---- prefetch XW for my 2 gate cells ----
        const float* XWt = XW + (size_t)t*BB*G4;
        const int c0 = tid, c1 = tid + 256;      // cell = b*32 + n
        float xw0 = __ldcg(XWt + (size_t)(c0 >> 5)*G4
                           + ((c0 & 31) >> 3)*HID + ub + (c0 & 7));
        float xw1 = __ldcg(XWt + (size_t)(c1 >> 5)*G4
                           + ((c1 & 31) >> 3)*HID + ub + (c1 & 7));

        // ---- mma over this warp's K slice (split hi/lo accumulators) ----
        float acch[4][4], accl[4][4];
#pragma unroll
        for(int ni=0;ni<4;ni++)
#pragma unroll
            for(int q=0;q<4;q++){ acch[ni][q] = 0.f; accl[ni][q] = 0.f; }

        const int kbase = w*128;
#pragma unroll 4
        for(int kk = 0; kk < 16; kk++){
            int k = kbase + kk*8;
            uint32_t ah[4], al[4];
            tsplit(h_s[ r     *WS_STR + k + cc],     ah[0], al[0]);
            tsplit(h_s[(r + 8)*WS_STR + k + cc],     ah[1], al[1]);
            tsplit(h_s[ r     *WS_STR + k + 4 + cc], ah[2], al[2]);
            tsplit(h_s[(r + 8)*WS_STR + k + 4 + cc], ah[3], al[3]);
            uint32_t bf[4][2];
#pragma unroll
            for(int ni=0;ni<4;ni++){
                bf[ni][0] = __float_as_uint(w_s[(ni*8 + r)*WS_STR + k + cc]);
                bf[ni][1] = __float_as_uint(w_s[(ni*8 + r)*WS_STR + k + 4 + cc]);
            }
#pragma unroll
            for(int ni=0;ni<4;ni++){
                mma_tf32(acch[ni], ah, bf[ni]);
                mma_tf32(accl[ni], al, bf[ni]);
            }
        }

        // ---- write partials: part[w][b][n] (stride 33) ----
#pragma unroll
        for(int ni=0;ni<4;ni++){
            int n0 = ni*8 + 2*cc;
            part[w*528 +  r     *33 + n0    ] = acch[ni][0] + accl[ni][0];
            part[w*528 +  r     *33 + n0 + 1] = acch[ni][1] + accl[ni][1];
            part[w*528 + (r + 8)*33 + n0    ] = acch[ni][2] + accl[ni][2];
            part[w*528 + (r + 8)*33 + n0 + 1] = acch[ni][3] + accl[ni][3];
        }
        __syncthreads();

        // ---- reduce 8 partials + XW -> gates[n][b] ----
        {
            int b0 = c0 >> 5, n0 = c0 & 31;
            int b1 = c1 >> 5, n1 = c1 & 31;
            float s0 = xw0, s1 = xw1;
#pragma unroll
            for(int ww = 0; ww < 8; ww++){
                s0 += part[ww*528 + b0*33 + n0];
                s1 += part[ww*528 + b1*33 + n1];
            }
            gates[n0*16 + b0] = s0;
            gates[n1*16 + b1] = s1;
        }
        __syncthreads();

        // ---- cell update (threads 0..127 own one (unit, batch)) ----
        if(tid < 128){
            float iv = gates[(0*8 + ul)*16 + bb2];
            float fv = gates[(1*8 + ul)*16 + bb2];
            float gv = gates[(2*8 + ul)*16 + bb2];
            float ov = gates[(3*8 + ul)*16 + bb2];
            iv = 1.f/(1.f + __expf(-iv));
            fv = 1.f/(1.f + __expf(-fv));
            ov = 1.f/(1.f + __expf(-ov));
            gv = tanhf(gv);
            float cn = fv*creg + iv*gv;
            float hn = ov*tanhf(cn);
            creg = cn;
            int u = ub + ul;
            Y[(size_t)t*BB*HID + bb2*HID + u] = hn;
            if(t == TT-1){
                hT[bb2*HID + u] = hn;
                cT[bb2*HID + u] = cn;
            }
        }

        // ---- grid barrier (release Y writes of step t) ----
        __syncthreads();
        if(tid == 0){
            __threadfence();
            atomicAdd(&g_cnt, 1u);
            unsigned target = (unsigned)(t + 1) * (unsigned)NB;
            while(*(volatile unsigned*)&g_cnt < target) {}
            __threadfence();
        }
        __syncthreads();
    }
}

// ---------------- log_softmax: online max+sum (2 passes total) --------------
__global__ void logsoftmax_k(float* __restrict__ p0){
    __shared__ float redm[33], reds[32];
    int row = blockIdx.x;
    float* p = p0 + (size_t)row*(size_t)VOC;
    int tid = threadIdx.x, lane = tid & 31, w = tid >> 5;
    int nthr = blockDim.x, nw = nthr >> 5;

    // pass 1: online (max, sum) over strided elements
    float m = -3.4e38f, s = 0.f;
    for(int i = tid; i < VOC; i += nthr){
        float x = p[i];
        if(x > m){ s = s*__expf(m - x) + 1.f; m = x; }
        else       s += __expf(x - m);
    }
    // warp combine
#pragma unroll
    for(int o=16;o>0;o>>=1){
        float m2 = __shfl_xor_sync(0xffffffffu, m, o);
        float s2 = __shfl_xor_sync(0xffffffffu, s, o);
        float M = fmaxf(m, m2);
        s = s*__expf(m - M) + s2*__expf(m2 - M);
        m = M;
    }
    if(lane == 0){ redm[w] = m; reds[w] = s; }
    __syncthreads();
    if(tid == 0){
        float M = redm[0], S = reds[0];
        for(int i=1;i<nw;i++){
            float M2 = fmaxf(M, redm[i]);
            S = S*__expf(M - M2) + reds[i]*__expf(redm[i] - M2);
            M = M2;
        }
        redm[32] = M + logf(S);
    }
    __syncthreads();
    float lse = redm[32];
    for(int i = tid; i < VOC; i += nthr) p[i] -= lse;
}

// ---------------- launcher ---------------------------------------------------
extern "C" void kernel_launch(void* const* d_in, const int* in_sizes, int n_in,
                              void* d_out, int out_size)
{
    const int*   tokens = (const int*)  d_in[0];
    const float* embW   = (const float*)d_in[1];
    const float* Wih    = (const float*)d_in[2];
    const float* Whh    = (const float*)d_in[3];
    const float* bih    = (const float*)d_in[4];
    const float* bhh    = (const float*)d_in[5];
    const float* decW   = (const float*)d_in[6];
    const float* decb   = (const float*)d_in[7];
    float* out = (float*)d_out;

    float *pEmb,*pY,*pXW;
    cudaGetSymbolAddress((void**)&pEmb, g_emb);
    cudaGetSymbolAddress((void**)&pY,   g_Y);
    cudaGetSymbolAddress((void**)&pXW,  g_XW);

    const int GEMM_SMEM = NSTG*STG_F*4;          // 110592 B
    cudaFuncSetAttribute(gemm_tc, cudaFuncAttributeMaxDynamicSharedMemorySize,
                         GEMM_SMEM);
    cudaFuncSetAttribute(lstm_seq, cudaFuncAttributeMaxDynamicSharedMemorySize,
                         LSTM_SMEM);

    embed_k<<<TB, 256>>>(tokens, embW, pEmb);

    for(int l = 0; l < 2; l++){
        const float* Xin = (l == 0) ? pEmb : pY;          // layer0 out at pY
        float* Yl = pY + (size_t)l*TB*HID;
        gemm_tc<<<dim3(G4/128, TB/128), 256, GEMM_SMEM>>>(
            Xin, Wih + (size_t)l*G4*HID, pXW,
            bih + l*G4, bhh + l*G4, G4, HID);
        reset_cnt<<<1, 1>>>();
        lstm_seq<<<128, 256, LSTM_SMEM>>>(
            Whh + (size_t)l*G4*HID, pXW, Yl,
            out + LOGITS + (size_t)l*BB*HID,
            out + LOGITS + (size_t)(2 + l)*BB*HID);
    }

    // tf32 tensor-core decoder GEMM: 2048 x 50257 x 1024
    gemm_tc<<<dim3((VOC + 127)/128, TB/128), 256, GEMM_SMEM>>>(
        pY + (size_t)TB*HID, decW, out, decb, nullptr, VOC, HID);

    logsoftmax_k<<<TB, 512>>>(out);
}

// round 11
// speedup vs baseline: 2.4402x; 1.0343x over previous
#include <cuda_runtime.h>
#include <cstdint>

#define TT   128
#define BB   16
#define HID  1024
#define G4   4096
#define VOC  50257
#define TB   (TT*BB)                 // 2048 rows
#define LOGITS ((size_t)TB*(size_t)VOC)

// ---------------- scratch (device globals; no allocation allowed) ----------
__device__ float g_emb[TB*HID];      // embedded input          8 MB
__device__ float g_Y[2*TB*HID];      // per-layer LSTM outputs 16 MB
__device__ float g_XW[TB*G4];        // input projections      32 MB
__device__ unsigned g_cnt;           // barrier arrival counter
__device__ unsigned g_pad[64];       // keep g_rel on a different 128B line
__device__ unsigned g_rel;           // barrier release generation

// ---------------- tf32 / cp.async helpers -----------------------------------
__device__ __forceinline__ uint32_t f2t(float x){
    uint32_t u;
    asm("cvt.rna.tf32.f32 %0, %1;" : "=r"(u) : "f"(x));
    return u;
}
// split fp32 into tf32 hi + tf32 lo (hi+lo ~ exact)
__device__ __forceinline__ void tsplit(float x, uint32_t& hi, uint32_t& lo){
    hi = f2t(x);
    lo = f2t(x - __uint_as_float(hi));
}
__device__ __forceinline__ void mma_tf32(float* c, const uint32_t* a,
                                         const uint32_t* b){
    asm volatile(
        "mma.sync.aligned.m16n8k8.row.col.f32.tf32.tf32.f32 "
        "{%0,%1,%2,%3}, {%4,%5,%6,%7}, {%8,%9}, {%0,%1,%2,%3};"
        : "+f"(c[0]), "+f"(c[1]), "+f"(c[2]), "+f"(c[3])
        : "r"(a[0]), "r"(a[1]), "r"(a[2]), "r"(a[3]), "r"(b[0]), "r"(b[1]));
}
__device__ __forceinline__ uint32_t smem_u32(const void* p){
    uint32_t a;
    asm("{ .reg .u64 t; cvta.to.shared.u64 t, %1; cvt.u32.u64 %0, t; }"
        : "=r"(a) : "l"(p));
    return a;
}
__device__ __forceinline__ void cpa16(uint32_t dst, const void* src, int sz){
    asm volatile("cp.async.cg.shared.global [%0], [%1], 16, %2;"
                 :: "r"(dst), "l"(src), "r"(sz) : "memory");
}

// ---------------- small utility kernels ------------------------------------
__global__ void reset_cnt(){ g_cnt = 0u; g_rel = 0u; }

__global__ void embed_k(const int* __restrict__ tokens,
                        const float* __restrict__ embW,
                        float* __restrict__ X){
    int row = blockIdx.x;                    // row = t*16 + b
    int tok = tokens[row];
    const float4* src = (const float4*)(embW + (size_t)tok*HID);
    float4* dst = (float4*)(X + (size_t)row*HID);
    for(int i = threadIdx.x; i < HID/4; i += blockDim.x) dst[i] = src[i];
}

// in-place tf32 truncation (rna); idempotent, so safe in place
__global__ void trunc_k(float* p, int n4){
    int i = blockIdx.x*blockDim.x + threadIdx.x;
    if(i < n4){
        float4 v = ((float4*)p)[i];
        v.x = __uint_as_float(f2t(v.x));
        v.y = __uint_as_float(f2t(v.y));
        v.z = __uint_as_float(f2t(v.z));
        v.w = __uint_as_float(f2t(v.w));
        ((float4*)p)[i] = v;
    }
}

// ---------------- tf32 tensor-core GEMM, 3-stage cp.async pipeline ----------
// C[M,N] = A[M,K] * B[N,K]^T + b1[n] (+ b2[n]).  NT, both K-contiguous.
// A must be PRE-TRUNCATED to tf32 (raw-bit reload, no cvt); B cvt'd per frag.
#define TCP 36                       // padded smem row stride (floats)
#define STG_F (2*128*TCP)            // floats per stage (As + Bs)
#define NSTG 3

__device__ __forceinline__ void g_issue(const float* A, const float* Bm,
                                        float* As, float* Bs,
                                        int bm, int bn, int kt, int N, int K,
                                        int lm, int lq0)
{
    uint32_t sA = smem_u32(As), sB = smem_u32(Bs);
#pragma unroll
    for(int h = 0; h < 4; h++){
        int q = lq0 + h;
        cpa16(sA + (uint32_t)(lm*TCP + q*4)*4,
              A + (size_t)(bm + lm)*K + kt + q*4, 16);
        int rowb = bn + lm;
        int ok = (rowb < N) ? 16 : 0;
        cpa16(sB + (uint32_t)(lm*TCP + q*4)*4,
              Bm + (size_t)(ok ? rowb : 0)*K + kt + q*4, ok);
    }
    asm volatile("cp.async.commit_group;" ::: "memory");
}

__global__ __launch_bounds__(256, 2)
void gemm_tc(const float* __restrict__ A, const float* __restrict__ Bm,
             float* __restrict__ C, const float* __restrict__ b1,
             const float* __restrict__ b2, int N, int K)
{
    extern __shared__ float smp[];
    const int tid = threadIdx.x;
    const int wid = tid >> 5, lane = tid & 31;
    const int r = lane >> 2, cc = lane & 3;
    const int wm = (wid & 1) * 64;
    const int wn = (wid >> 1) * 32;
    const int bm = blockIdx.y * 128, bn = blockIdx.x * 128;
    const int lm = tid >> 1;
    const int lq0 = (tid & 1) * 4;

    float acc[4][4][4];
#pragma unroll
    for(int mi=0;mi<4;mi++)
#pragma unroll
        for(int ni=0;ni<4;ni++)
#pragma unroll
            for(int q=0;q<4;q++) acc[mi][ni][q] = 0.f;

    const int nkt = K >> 5;
    g_issue(A, Bm, smp, smp + 128*TCP, bm, bn, 0, N, K, lm, lq0);
    if(nkt > 1){
        float* S1 = smp + STG_F;
        g_issue(A, Bm, S1, S1 + 128*TCP, bm, bn, 32, N, K, lm, lq0);
    }

    for(int it = 0; it < nkt; it++){
        int s = it % NSTG;
        if(it + 1 < nkt){
            asm volatile("cp.async.wait_group 1;" ::: "memory");
        } else {
            asm volatile("cp.async.wait_group 0;" ::: "memory");
        }
        __syncthreads();                       // single sync per iter
        if(it + 2 < nkt){
            float* Sn = smp + ((it+2) % NSTG)*STG_F;
            g_issue(A, Bm, Sn, Sn + 128*TCP, bm, bn, (it+2)*32, N, K, lm, lq0);
        }

        const float* As = smp + s*STG_F;
        const float* Bs = As + 128*TCP;
#pragma unroll
        for(int ks = 0; ks < 4; ks++){
            const int k0 = ks*8;
            uint32_t af[4][4], bf[4][2];
#pragma unroll
            for(int mi=0;mi<4;mi++){
                const float* ap = As + (wm + mi*16 + r)*TCP + k0 + cc;
                af[mi][0] = __float_as_uint(ap[0]);          // pre-truncated
                af[mi][1] = __float_as_uint(ap[8*TCP]);
                af[mi][2] = __float_as_uint(ap[4]);
                af[mi][3] = __float_as_uint(ap[8*TCP + 4]);
            }
#pragma unroll
            for(int ni=0;ni<4;ni++){
                const float* bp = Bs + (wn + ni*8 + r)*TCP + k0 + cc;
                bf[ni][0] = f2t(bp[0]);
                bf[ni][1] = f2t(bp[4]);
            }
#pragma unroll
            for(int mi=0;mi<4;mi++)
#pragma unroll
                for(int ni=0;ni<4;ni++)
                    mma_tf32(acc[mi][ni], af[mi], bf[ni]);
        }
    }

#pragma unroll
    for(int ni=0;ni<4;ni++){
        int col = bn + wn + ni*8 + 2*cc;
        if(col >= N) continue;
        bool c1ok = (col + 1 < N);
        float bb0 = b1[col] + (b2 ? b2[col] : 0.f);
        float bb1 = c1ok ? (b1[col+1] + (b2 ? b2[col+1] : 0.f)) : 0.f;
#pragma unroll
        for(int mi=0;mi<4;mi++){
            size_t row0 = (size_t)(bm + wm + mi*16 + r);
            float* p0 = C + row0*(size_t)N + col;
            float* p1 = C + (row0+8)*(size_t)N + col;
            p0[0] = acc[mi][ni][0] + bb0;
            if(c1ok) p0[1] = acc[mi][ni][1] + bb1;
            p1[0] = acc[mi][ni][2] + bb0;
            if(c1ok) p1[1] = acc[mi][ni][3] + bb1;
        }
    }
}

// ---------------- persistent LSTM layer, tensor-core recurrence -------------
// 128 blocks (co-resident), 256 threads. Grid barrier = arrival counter +
// separate release flag (read-only spin; no RMW contention on the spin line).
#define WS_STR 1028                          // smem row stride (floats)
#define LSTM_SMEM ((32*WS_STR + 16*WS_STR + 8*528 + 512)*4)   // 216320 B

__global__ __launch_bounds__(256, 1)
void lstm_seq(const float* __restrict__ Whh_l,
              const float* __restrict__ XW,
              float* __restrict__ Y,
              float* __restrict__ hT,
              float* __restrict__ cT)
{
    extern __shared__ float sm[];
    float* w_s   = sm;                       // 32 x WS_STR (tf32-as-f32)
    float* h_s   = sm + 32*WS_STR;           // 16 x WS_STR (fp32)
    float* part  = h_s + 16*WS_STR;          // 8 warps x (16 x 33)
    float* gates = part + 8*528;             // 32 x 16

    const int tid = threadIdx.x;
    const int w = tid >> 5, lane = tid & 31;
    const int r = lane >> 2, cc = lane & 3;
    const int ub = blockIdx.x*8;
    const int NB = gridDim.x;

    // ---- stage + tf32-truncate this block's 32 Whh rows (once) ----
    {
        const int row4 = HID/4;
        for(int i = tid; i < 32*row4; i += 256){
            int row = i / row4, c4 = i % row4;
            int gg = row >> 3, rr = row & 7;
            float4 v = ((const float4*)(Whh_l + (size_t)(gg*HID + ub + rr)*HID))[c4];
            float* dst = w_s + row*WS_STR + c4*4;
            dst[0] = __uint_as_float(f2t(v.x));
            dst[1] = __uint_as_float(f2t(v.y));
            dst[2] = __uint_as_float(f2t(v.z));
            dst[3] = __uint_as_float(f2t(v.w));
        }
    }

    float creg = 0.f;
    const int ul = tid >> 4, bb2 = tid & 15;     // cell-update mapping (tid<128)
    __syncthreads();

    for(int t = 0; t < TT; t++){
        // ---- stage h_prev (fp32) ----
        if(t == 0){
            float4 z = make_float4(0.f,0.f,0.f,0.f);
            for(int i = tid; i < BB*(HID/4); i += 256){
                int b = i / (HID/4), c4 = i % (HID/4);
                *(float4*)(h_s + b*WS_STR + c4*4) = z;
            }
        } else {
            const float4* src = (const float4*)(Y + (size_t)(t-1)*BB*HID);
            for(int i = tid; i < BB*(HID/4); i += 256){
                int b = i / (HID/4), c4 = i % (HID/4);
                *(float4*)(h_s + b*WS_STR + c4*4) = __ldcg(src + i);
            }
        }
        __syncthreads();

        // ---- prefetch XW for my 2 gate cells ----
        const float* XWt = XW + (size_t)t*BB*G4;
        const int c0 = tid, c1 = tid + 256;      // cell = b*32 + n
        float xw0 = __ldcg(XWt + (size_t)(c0 >> 5)*G4
                           + ((c0 & 31) >> 3)*HID + ub + (c0 & 7));
        float xw1 = __ldcg(XWt + (size_t)(c1 >> 5)*G4
                           + ((c1 & 31) >> 3)*HID + ub + (c1 & 7));

        // ---- mma over this warp's K slice (split hi/lo accumulators) ----
        float acch[4][4], accl[4][4];
#pragma unroll
        for(int ni=0;ni<4;ni++)
#pragma unroll
            for(int q=0;q<4;q++){ acch[ni][q] = 0.f; accl[ni][q] = 0.f; }

        const int kbase = w*128;
#pragma unroll 4
        for(int kk = 0; kk < 16; kk++){
            int k = kbase + kk*8;
            uint32_t ah[4], al[4];
            tsplit(h_s[ r     *WS_STR + k + cc],     ah[0], al[0]);
            tsplit(h_s[(r + 8)*WS_STR + k + cc],     ah[1], al[1]);
            tsplit(h_s[ r     *WS_STR + k + 4 + cc], ah[2], al[2]);
            tsplit(h_s[(r + 8)*WS_STR + k + 4 + cc], ah[3], al[3]);
            uint32_t bf[4][2];
#pragma unroll
            for(int ni=0;ni<4;ni++){
                bf[ni][0] = __float_as_uint(w_s[(ni*8 + r)*WS_STR + k + cc]);
                bf[ni][1] = __float_as_uint(w_s[(ni*8 + r)*WS_STR + k + 4 + cc]);
            }
#pragma unroll
            for(int ni=0;ni<4;ni++){
                mma_tf32(acch[ni], ah, bf[ni]);
                mma_tf32(accl[ni], al, bf[ni]);
            }
        }

        // ---- write partials: part[w][b][n] (stride 33) ----
#pragma unroll
        for(int ni=0;ni<4;ni++){
            int n0 = ni*8 + 2*cc;
            part[w*528 +  r     *33 + n0    ] = acch[ni][0] + accl[ni][0];
            part[w*528 +  r     *33 + n0 + 1] = acch[ni][1] + accl[ni][1];
            part[w*528 + (r + 8)*33 + n0    ] = acch[ni][2] + accl[ni][2];
            part[w*528 + (r + 8)*33 + n0 + 1] = acch[ni][3] + accl[ni][3];
        }
        __syncthreads();

        // ---- reduce 8 partials + XW -> gates[n][b] ----
        {
            int b0 = c0 >> 5, n0 = c0 & 31;
            int b1 = c1 >> 5, n1 = c1 & 31;
            float s0 = xw0, s1 = xw1;
#pragma unroll
            for(int ww = 0; ww < 8; ww++){
                s0 += part[ww*528 + b0*33 + n0];
                s1 += part[ww*528 + b1*33 + n1];
            }
            gates[n0*16 + b0] = s0;
            gates[n1*16 + b1] = s1;
        }
        __syncthreads();

        // ---- cell update (threads 0..127 own one (unit, batch)) ----
        if(tid < 128){
            float iv = gates[(0*8 + ul)*16 + bb2];
            float fv = gates[(1*8 + ul)*16 + bb2];
            float gv = gates[(2*8 + ul)*16 + bb2];
            float ov = gates[(3*8 + ul)*16 + bb2];
            iv = 1.f/(1.f + __expf(-iv));
            fv = 1.f/(1.f + __expf(-fv));
            ov = 1.f/(1.f + __expf(-ov));
            gv = tanhf(gv);
            float cn = fv*creg + iv*gv;
            float hn = ov*tanhf(cn);
            creg = cn;
            int u = ub + ul;
            Y[(size_t)t*BB*HID + bb2*HID + u] = hn;
            if(t == TT-1){
                hT[bb2*HID + u] = hn;
                cT[bb2*HID + u] = cn;
            }
        }

        // ---- grid barrier: arrivals on g_cnt, read-only spin on g_rel ----
        __syncthreads();
        if(tid == 0){
            __threadfence();
            unsigned old = atomicAdd(&g_cnt, 1u);
            if(old == (unsigned)t*(unsigned)NB + (unsigned)(NB - 1)){
                atomicExch(&g_rel, (unsigned)(t + 1));      // release
            } else {
                while(*(volatile unsigned*)&g_rel <= (unsigned)t) {}
            }
            __threadfence();
        }
        __syncthreads();
    }
}

// ---------------- log_softmax: online max+sum (2 passes total) --------------
__global__ void logsoftmax_k(float* __restrict__ p0){
    __shared__ float redm[33], reds[32];
    int row = blockIdx.x;
    float* p = p0 + (size_t)row*(size_t)VOC;
    int tid = threadIdx.x, lane = tid & 31, w = tid >> 5;
    int nthr = blockDim.x, nw = nthr >> 5;

    float m = -3.4e38f, s = 0.f;
    for(int i = tid; i < VOC; i += nthr){
        float x = p[i];
        if(x > m){ s = s*__expf(m - x) + 1.f; m = x; }
        else       s += __expf(x - m);
    }
#pragma unroll
    for(int o=16;o>0;o>>=1){
        float m2 = __shfl_xor_sync(0xffffffffu, m, o);
        float s2 = __shfl_xor_sync(0xffffffffu, s, o);
        float M = fmaxf(m, m2);
        s = s*__expf(m - M) + s2*__expf(m2 - M);
        m = M;
    }
    if(lane == 0){ redm[w] = m; reds[w] = s; }
    __syncthreads();
    if(tid == 0){
        float M = redm[0], S = reds[0];
        for(int i=1;i<nw;i++){
            float M2 = fmaxf(M, redm[i]);
            S = S*__expf(M - M2) + reds[i]*__expf(redm[i] - M2);
            M = M2;
        }
        redm[32] = M + logf(S);
    }
    __syncthreads();
    float lse = redm[32];
    for(int i = tid; i < VOC; i += nthr) p[i] -= lse;
}

// ---------------- launcher ---------------------------------------------------
extern "C" void kernel_launch(void* const* d_in, const int* in_sizes, int n_in,
                              void* d_out, int out_size)
{
    const int*   tokens = (const int*)  d_in[0];
    const float* embW   = (const float*)d_in[1];
    const float* Wih    = (const float*)d_in[2];
    const float* Whh    = (const float*)d_in[3];
    const float* bih    = (const float*)d_in[4];
    const float* bhh    = (const float*)d_in[5];
    const float* decW   = (const float*)d_in[6];
    const float* decb   = (const float*)d_in[7];
    float* out = (float*)d_out;

    float *pEmb,*pY,*pXW;
    cudaGetSymbolAddress((void**)&pEmb, g_emb);
    cudaGetSymbolAddress((void**)&pY,   g_Y);
    cudaGetSymbolAddress((void**)&pXW,  g_XW);

    const int GEMM_SMEM = NSTG*STG_F*4;          // 110592 B
    cudaFuncSetAttribute(gemm_tc, cudaFuncAttributeMaxDynamicSharedMemorySize,
                         GEMM_SMEM);
    cudaFuncSetAttribute(lstm_seq, cudaFuncAttributeMaxDynamicSharedMemorySize,
                         LSTM_SMEM);

    const int N4 = TB*HID/4;                     // float4 count per activation

    embed_k<<<TB, 256>>>(tokens, embW, pEmb);
    trunc_k<<<(N4 + 255)/256, 256>>>(pEmb, N4);  // A of proj0 pre-truncated

    for(int l = 0; l < 2; l++){
        const float* Xin = (l == 0) ? pEmb : pY;          // layer0 out at pY
        float* Yl = pY + (size_t)l*TB*HID;
        gemm_tc<<<dim3(G4/128, TB/128), 256, GEMM_SMEM>>>(
            Xin, Wih + (size_t)l*G4*HID, pXW,
            bih + l*G4, bhh + l*G4, G4, HID);
        reset_cnt<<<1, 1>>>();
        lstm_seq<<<128, 256, LSTM_SMEM>>>(
            Whh + (size_t)l*G4*HID, pXW, Yl,
            out + LOGITS + (size_t)l*BB*HID,
            out + LOGITS + (size_t)(2 + l)*BB*HID);
        // pre-truncate this layer's output: it feeds only the next GEMM
        trunc_k<<<(N4 + 255)/256, 256>>>(Yl, N4);
    }

    // tf32 tensor-core decoder GEMM: 2048 x 50257 x 1024
    gemm_tc<<<dim3((VOC + 127)/128, TB/128), 256, GEMM_SMEM>>>(
        pY + (size_t)TB*HID, decW, out, decb, nullptr, VOC, HID);

    logsoftmax_k<<<TB, 512>>>(out);
}